// round 1
// baseline (speedup 1.0000x reference)
#include <cuda_runtime.h>

// Problem constants
#define BB 4
#define SS 2048
#define HH 8
#define DD 64
#define HID 512
#define MT (BB*SS)   // 8192 rows

// Scratch (static device globals; no allocation allowed)
__device__ float g_Q[BB*HH*SS*DD];
__device__ float g_K[BB*HH*SS*DD];
__device__ float g_V[BB*HH*SS*DD];
__device__ float g_C[MT*HID];

// ---------------------------------------------------------------------------
// GEMM: out = A[M,K] @ W[N,K]^T + bias[N]
// SPLIT=1: write head-split layout out[b,h,s,d]; SPLIT=0: plain [M,N].
// 64x64 tile, BK=16, 256 threads, 4x4 per thread.
// Smem staged transposed (As[k][m]) so inner loop is 2x LDS.128 + 16 FFMA.
// ---------------------------------------------------------------------------
template<int SPLIT>
__global__ __launch_bounds__(256)
void gemm_bias(const float* __restrict__ A, const float* __restrict__ W,
               const float* __restrict__ bias, float* __restrict__ out,
               int Kdim, int Ndim)
{
    __shared__ float As[16][68];
    __shared__ float Ws[16][68];
    const int tid = threadIdx.x;
    const int tx = tid & 15, ty = tid >> 4;
    const int m0 = blockIdx.x << 6, n0 = blockIdx.y << 6;
    const int lr = tid >> 2;          // 0..63 (row within tile)
    const int lc = (tid & 3) << 2;    // 0,4,8,12 (k offset)
    float acc[4][4] = {};

    const float* Aptr = A + (size_t)(m0 + lr) * Kdim + lc;
    const float* Wptr = W + (size_t)(n0 + lr) * Kdim + lc;

    for (int k0 = 0; k0 < Kdim; k0 += 16) {
        float4 av = *(const float4*)(Aptr + k0);
        float4 wv = *(const float4*)(Wptr + k0);
        As[lc+0][lr] = av.x; As[lc+1][lr] = av.y;
        As[lc+2][lr] = av.z; As[lc+3][lr] = av.w;
        Ws[lc+0][lr] = wv.x; Ws[lc+1][lr] = wv.y;
        Ws[lc+2][lr] = wv.z; Ws[lc+3][lr] = wv.w;
        __syncthreads();
        #pragma unroll
        for (int kk = 0; kk < 16; kk++) {
            float4 a4 = *(const float4*)&As[kk][ty << 2];
            float4 w4 = *(const float4*)&Ws[kk][tx << 2];
            float a[4] = {a4.x, a4.y, a4.z, a4.w};
            float w[4] = {w4.x, w4.y, w4.z, w4.w};
            #pragma unroll
            for (int i = 0; i < 4; i++)
                #pragma unroll
                for (int j = 0; j < 4; j++)
                    acc[i][j] = fmaf(a[i], w[j], acc[i][j]);
        }
        __syncthreads();
    }

    const int ncol = n0 + (tx << 2);
    float b0 = bias[ncol+0], b1 = bias[ncol+1], b2 = bias[ncol+2], b3 = bias[ncol+3];
    #pragma unroll
    for (int i = 0; i < 4; i++) {
        int m = m0 + (ty << 2) + i;
        float4 o;
        o.x = acc[i][0] + b0; o.y = acc[i][1] + b1;
        o.z = acc[i][2] + b2; o.w = acc[i][3] + b3;
        if (SPLIT) {
            int b = m >> 11;            // /S (2048)
            int s = m & 2047;
            int h = n0 >> 6;            // whole block is one head
            float* dst = out + (((size_t)(b*HH + h) * SS) + s) * DD + (tx << 2);
            *(float4*)dst = o;
        } else {
            *(float4*)&out[(size_t)m * Ndim + ncol] = o;
        }
    }
}

// ---------------------------------------------------------------------------
// Flash attention: one block per (b, h, 64-query tile). Streams 64-key tiles.
// 256 threads (16x16), 4x4 microtiles for both QK^T and PV.
// Online softmax; stats for 64 rows kept in smem, 4 threads per row.
// ---------------------------------------------------------------------------
__global__ __launch_bounds__(256)
void attn_kernel(const float* __restrict__ Q, const float* __restrict__ K,
                 const float* __restrict__ V, float* __restrict__ ctx)
{
    extern __shared__ float sm[];
    const int STR = 68;
    float* Qs  = sm;
    float* Ks  = sm + 64*STR;
    float* Vs  = sm + 2*64*STR;
    float* Ps  = sm + 3*64*STR;
    float* m_sh = sm + 4*64*STR;
    float* l_sh = m_sh + 64;
    float* c_sh = l_sh + 64;

    const int tid = threadIdx.x;
    const int tx = tid & 15, ty = tid >> 4;
    const int b = blockIdx.z, h = blockIdx.y;
    const int q0 = blockIdx.x << 6;
    const float* Qb = Q + ((size_t)(b*HH + h) * SS + q0) * DD;
    const float* Kb = K + (size_t)(b*HH + h) * SS * DD;
    const float* Vb = V + (size_t)(b*HH + h) * SS * DD;

    // Load Q tile (pre-scaled by 1/sqrt(64) = 0.125)
    #pragma unroll
    for (int i = 0; i < 4; i++) {
        int idx = tid + (i << 8);
        int r = idx >> 4;
        int c = (idx & 15) << 2;
        float4 qv = *(const float4*)&Qb[r*DD + c];
        Qs[r*STR+c+0] = qv.x * 0.125f; Qs[r*STR+c+1] = qv.y * 0.125f;
        Qs[r*STR+c+2] = qv.z * 0.125f; Qs[r*STR+c+3] = qv.w * 0.125f;
    }
    if (tid < 64) { m_sh[tid] = -3.0e38f; l_sh[tid] = 0.0f; }
    float acc[4][4] = {};

    for (int t0 = 0; t0 < SS; t0 += 64) {
        // Load K,V tiles
        #pragma unroll
        for (int i = 0; i < 4; i++) {
            int idx = tid + (i << 8);
            int r = idx >> 4;
            int c = (idx & 15) << 2;
            float4 kv = *(const float4*)&Kb[(size_t)(t0+r)*DD + c];
            Ks[r*STR+c+0] = kv.x; Ks[r*STR+c+1] = kv.y;
            Ks[r*STR+c+2] = kv.z; Ks[r*STR+c+3] = kv.w;
            float4 vv = *(const float4*)&Vb[(size_t)(t0+r)*DD + c];
            Vs[r*STR+c+0] = vv.x; Vs[r*STR+c+1] = vv.y;
            Vs[r*STR+c+2] = vv.z; Vs[r*STR+c+3] = vv.w;
        }
        __syncthreads();

        // S = (Q*scale) @ K^T  (64x64)
        float sacc[4][4] = {};
        #pragma unroll
        for (int k = 0; k < 64; k++) {
            float a[4], kb[4];
            #pragma unroll
            for (int i = 0; i < 4; i++) a[i]  = Qs[((ty<<2)+i)*STR + k];
            #pragma unroll
            for (int j = 0; j < 4; j++) kb[j] = Ks[((tx<<2)+j)*STR + k];
            #pragma unroll
            for (int i = 0; i < 4; i++)
                #pragma unroll
                for (int j = 0; j < 4; j++)
                    sacc[i][j] = fmaf(a[i], kb[j], sacc[i][j]);
        }
        #pragma unroll
        for (int i = 0; i < 4; i++)
            #pragma unroll
            for (int j = 0; j < 4; j++)
                Ps[((ty<<2)+i)*STR + (tx<<2)+j] = sacc[i][j];
        __syncthreads();

        // Online softmax: 4 threads per row, 16 cols each
        {
            const int row = tid >> 2;
            const int p0 = (tid & 3) << 4;
            float* prow = Ps + row*STR + p0;
            float mx = -3.0e38f;
            #pragma unroll
            for (int c = 0; c < 16; c++) mx = fmaxf(mx, prow[c]);
            mx = fmaxf(mx, __shfl_xor_sync(0xffffffffu, mx, 1));
            mx = fmaxf(mx, __shfl_xor_sync(0xffffffffu, mx, 2));
            const float m_old = m_sh[row];
            const float m_new = fmaxf(m_old, mx);
            float sum = 0.0f;
            #pragma unroll
            for (int c = 0; c < 16; c++) {
                float p = __expf(prow[c] - m_new);
                prow[c] = p;
                sum += p;
            }
            sum += __shfl_xor_sync(0xffffffffu, sum, 1);
            sum += __shfl_xor_sync(0xffffffffu, sum, 2);
            if ((tid & 3) == 0) {
                float corr = __expf(m_old - m_new);
                c_sh[row] = corr;
                l_sh[row] = l_sh[row] * corr + sum;
                m_sh[row] = m_new;
            }
        }
        __syncthreads();

        // Rescale accumulator, then O += P @ V
        float cr[4];
        #pragma unroll
        for (int i = 0; i < 4; i++) cr[i] = c_sh[(ty<<2)+i];
        #pragma unroll
        for (int i = 0; i < 4; i++)
            #pragma unroll
            for (int j = 0; j < 4; j++)
                acc[i][j] *= cr[i];
        #pragma unroll
        for (int k = 0; k < 64; k++) {
            float4 v4 = *(const float4*)&Vs[k*STR + (tx<<2)];
            float v[4] = {v4.x, v4.y, v4.z, v4.w};
            float p[4];
            #pragma unroll
            for (int i = 0; i < 4; i++) p[i] = Ps[((ty<<2)+i)*STR + k];
            #pragma unroll
            for (int i = 0; i < 4; i++)
                #pragma unroll
                for (int j = 0; j < 4; j++)
                    acc[i][j] = fmaf(p[i], v[j], acc[i][j]);
        }
        __syncthreads();
    }

    // Epilogue: normalize and write ctx in [B, S, HIDDEN] layout
    #pragma unroll
    for (int i = 0; i < 4; i++) {
        int r = (ty << 2) + i;
        float inv = 1.0f / l_sh[r];
        float4 o;
        o.x = acc[i][0] * inv; o.y = acc[i][1] * inv;
        o.z = acc[i][2] * inv; o.w = acc[i][3] * inv;
        *(float4*)&ctx[((size_t)b * SS + q0 + r) * HID + h*DD + (tx << 2)] = o;
    }
}

// ---------------------------------------------------------------------------
extern "C" void kernel_launch(void* const* d_in, const int* in_sizes, int n_in,
                              void* d_out, int out_size)
{
    (void)in_sizes; (void)n_in; (void)out_size;
    const float* x  = (const float*)d_in[0];
    const float* Wq = (const float*)d_in[1];
    const float* bq = (const float*)d_in[2];
    const float* Wk = (const float*)d_in[3];
    const float* bk = (const float*)d_in[4];
    const float* Wv = (const float*)d_in[5];
    const float* bv = (const float*)d_in[6];
    const float* Wo = (const float*)d_in[7];
    const float* bo = (const float*)d_in[8];
    float* out = (float*)d_out;

    float *Qp, *Kp, *Vp, *Cp;
    cudaGetSymbolAddress((void**)&Qp, g_Q);
    cudaGetSymbolAddress((void**)&Kp, g_K);
    cudaGetSymbolAddress((void**)&Vp, g_V);
    cudaGetSymbolAddress((void**)&Cp, g_C);

    dim3 ggrid(MT/64, HID/64);
    gemm_bias<1><<<ggrid, 256>>>(x, Wq, bq, Qp, HID, HID);
    gemm_bias<1><<<ggrid, 256>>>(x, Wk, bk, Kp, HID, HID);
    gemm_bias<1><<<ggrid, 256>>>(x, Wv, bv, Vp, HID, HID);

    size_t smem = (size_t)(4*64*68 + 3*64) * sizeof(float);   // 70400 B
    cudaFuncSetAttribute(attn_kernel, cudaFuncAttributeMaxDynamicSharedMemorySize, (int)smem);
    attn_kernel<<<dim3(SS/64, HH, BB), 256, smem>>>(Qp, Kp, Vp, Cp);

    gemm_bias<0><<<ggrid, 256>>>(Cp, Wo, bo, out, HID, HID);
}

// round 4
// speedup vs baseline: 3.4652x; 3.4652x over previous
#include <cuda_runtime.h>
#include <cstdint>

// ---------------- problem constants ----------------
#define BB 4
#define SS 2048
#define HH 8
#define DD 64
#define HID 512
#define MT (BB*SS)   // 8192

// scratch
__device__ float g_Q[MT*HID];   // [b,h,s,d]
__device__ float g_K[MT*HID];   // [b,h,s,d]
__device__ float g_V[MT*HID];   // [b,h,s,d]
__device__ float g_C[MT*HID];   // ctx [b,s,hid]

__device__ __forceinline__ float tf32r(float x){   // round-to-nearest tf32
    float r; asm("cvt.rna.tf32.f32 %0, %1;" : "=f"(r) : "f"(x)); return r;
}
__device__ __forceinline__ uint32_t f2u(float x){ return __float_as_uint(x); }

// mma.sync m16n8k8 tf32: C(16x8) += A(16x8,row) * B(8x8,col)
__device__ __forceinline__ void mma8(float* c, const uint32_t* a, const uint32_t* b){
    asm volatile("mma.sync.aligned.m16n8k8.row.col.f32.tf32.tf32.f32 "
        "{%0,%1,%2,%3}, {%4,%5,%6,%7}, {%8,%9}, {%0,%1,%2,%3};"
        : "+f"(c[0]), "+f"(c[1]), "+f"(c[2]), "+f"(c[3])
        : "r"(a[0]), "r"(a[1]), "r"(a[2]), "r"(a[3]), "r"(b[0]), "r"(b[1]));
}

// ---------------------------------------------------------------------------
// GEMM: out = A[M,512] @ W[Nblk,512]^T + bias.  CTA tile 128x128, BK=32.
// 8 warps = 4(M) x 2(N); warp tile 32x64 = 2 mtiles x 8 ntiles of 16x8.
// Pad-36 smem rows: fragment LDS bank = (4*row + col) % 32 -> conflict-free.
// MODE 0: out[m][512]   MODE 1: split-head [b,h,s,d]
// ---------------------------------------------------------------------------
#define GPAD 36
template<int MODE>
__global__ __launch_bounds__(256, 2)
void gemm_mma(const float* __restrict__ A, const float* __restrict__ W,
              const float* __restrict__ bias, float* __restrict__ out)
{
    extern __shared__ float sm[];
    float* As = sm;                 // [128][36]
    float* Ws = sm + 128*GPAD;      // [128][36]
    float* bs = sm + 2*128*GPAD;    // [128]

    const int tid = threadIdx.x;
    const int lane = tid & 31, warp = tid >> 5;
    const int g = lane >> 2, t4 = lane & 3;
    const int warpM = warp >> 1, warpN = warp & 1;
    const int m0 = blockIdx.x << 7, n0 = blockIdx.y << 7;

    if (tid < 128) bs[tid] = bias[n0 + tid];

    float c[2][8][4];
    #pragma unroll
    for (int i = 0; i < 2; i++)
        #pragma unroll
        for (int j = 0; j < 8; j++)
            #pragma unroll
            for (int k = 0; k < 4; k++) c[i][j][k] = 0.0f;

    const int lr = tid >> 3;           // 0..31
    const int lc = (tid & 7) << 2;     // 0..28
    const float* Ap = A + (size_t)(m0 + lr) * HID + lc;
    const float* Wp = W + (size_t)(n0 + lr) * HID + lc;

    for (int k0 = 0; k0 < HID; k0 += 32) {
        #pragma unroll
        for (int i = 0; i < 4; i++) {
            float4 v = *(const float4*)(Ap + (size_t)i*32*HID + k0);
            v.x = tf32r(v.x); v.y = tf32r(v.y); v.z = tf32r(v.z); v.w = tf32r(v.w);
            *(float4*)&As[(lr + i*32)*GPAD + lc] = v;
            float4 u = *(const float4*)(Wp + (size_t)i*32*HID + k0);
            u.x = tf32r(u.x); u.y = tf32r(u.y); u.z = tf32r(u.z); u.w = tf32r(u.w);
            *(float4*)&Ws[(lr + i*32)*GPAD + lc] = u;
        }
        __syncthreads();
        #pragma unroll
        for (int ks = 0; ks < 4; ks++) {
            uint32_t af[2][4];
            #pragma unroll
            for (int mt = 0; mt < 2; mt++) {
                const int row = warpM*32 + mt*16 + g;
                const int base = row*GPAD + ks*8 + t4;
                af[mt][0] = f2u(As[base]);
                af[mt][1] = f2u(As[base + 8*GPAD]);
                af[mt][2] = f2u(As[base + 4]);
                af[mt][3] = f2u(As[base + 8*GPAD + 4]);
            }
            uint32_t bf[8][2];
            #pragma unroll
            for (int nt = 0; nt < 8; nt++) {
                const int n = warpN*64 + nt*8 + g;
                const int bb = n*GPAD + ks*8 + t4;
                bf[nt][0] = f2u(Ws[bb]);
                bf[nt][1] = f2u(Ws[bb + 4]);
            }
            #pragma unroll
            for (int mt = 0; mt < 2; mt++)
                #pragma unroll
                for (int nt = 0; nt < 8; nt++)
                    mma8(c[mt][nt], af[mt], bf[nt]);
        }
        __syncthreads();
    }

    // epilogue
    #pragma unroll
    for (int mt = 0; mt < 2; mt++) {
        const int row = m0 + warpM*32 + mt*16 + g;
        #pragma unroll
        for (int nt = 0; nt < 8; nt++) {
            const int lcol = warpN*64 + nt*8 + 2*t4;
            const float b0 = bs[lcol], b1 = bs[lcol+1];
            float2 v0 = make_float2(c[mt][nt][0] + b0, c[mt][nt][1] + b1);
            float2 v1 = make_float2(c[mt][nt][2] + b0, c[mt][nt][3] + b1);
            if (MODE == 0) {
                *(float2*)&out[(size_t)row * HID + n0 + lcol] = v0;
                *(float2*)&out[(size_t)(row+8) * HID + n0 + lcol] = v1;
            } else {
                const int bi = row >> 11, s = row & 2047;
                const int cg = n0 + lcol;
                const int h = cg >> 6, d = cg & 63;
                float* p = out + (((size_t)(bi*HH + h) * SS) + s) * DD + d;
                *(float2*)p = v0;
                *(float2*)(p + 8*DD) = v1;
            }
        }
    }
}

// ---------------------------------------------------------------------------
// Flash attention, mma.sync tf32.
// CTA: 256 thr (8 warps), 128-query tile of one (b,h). KV tiles of 64 keys.
// S warp layout: 4(M)x2(N) -> warp 32q x 32keys (2 mtiles x 4 ntiles).
// PV warp layout: same warps over (q,d): warp 32q x 32d.
// O accumulator + softmax stats in registers (documented mma frag layout).
// ---------------------------------------------------------------------------
#define APAD 68
__global__ __launch_bounds__(256, 2)
void attn_mma(const float* __restrict__ Q, const float* __restrict__ K,
              const float* __restrict__ V, float* __restrict__ ctx)
{
    extern __shared__ float sm[];
    float* Qs = sm;                       // [128][68]
    float* Ks = sm + 8704;                // [64][68]
    float* Vs = sm + 13056;               // [64][68]  transposed: [d][key]
    float* Ps = sm + 17408;               // [128][68]
    float* corr_s = sm + 26112;           // [128]
    float* l_s    = sm + 26240;           // [128]

    const int tid = threadIdx.x;
    const int lane = tid & 31, warp = tid >> 5;
    const int g = lane >> 2, t4 = lane & 3;
    const int warpM = warp >> 1, warpN = warp & 1;
    const int b = blockIdx.z, h = blockIdx.y;
    const int q0 = blockIdx.x << 7;

    const float* Qg = Q + ((size_t)(b*HH + h) * SS + q0) * DD;
    const float* Kg = K + (size_t)(b*HH + h) * SS * DD;
    const float* Vg = V + (size_t)(b*HH + h) * SS * DD;

    // load Q (scaled by 0.125, tf32-rounded)
    {
        const int qr = tid >> 1, qc0 = (tid & 1) << 5;
        #pragma unroll
        for (int i = 0; i < 8; i++) {
            float4 v = *(const float4*)(Qg + (size_t)qr*DD + qc0 + i*4);
            v.x = tf32r(v.x * 0.125f); v.y = tf32r(v.y * 0.125f);
            v.z = tf32r(v.z * 0.125f); v.w = tf32r(v.w * 0.125f);
            *(float4*)&Qs[qr*APAD + qc0 + i*4] = v;
        }
    }

    const int srow = tid >> 1, shalf = tid & 1;
    float m_i = -3.0e38f, l_i = 0.0f;
    float o[2][4][4];
    #pragma unroll
    for (int i = 0; i < 2; i++)
        #pragma unroll
        for (int j = 0; j < 4; j++)
            #pragma unroll
            for (int k = 0; k < 4; k++) o[i][j][k] = 0.0f;

    #pragma unroll 1
    for (int t = 0; t < SS/64; t++) {
        __syncthreads();   // previous PV reads of Ks/Vs/Ps complete
        // load K tile [64 keys][64 d] and V tile transposed [64 d][64 keys]
        {
            const int r = tid >> 2;             // 0..63
            const int cb = (tid & 3) << 4;      // 0,16,32,48
            const float* kp = Kg + ((size_t)(t*64 + r)) * DD + cb;
            const float* vp = Vg + ((size_t)(t*64 + r)) * DD + cb;
            #pragma unroll
            for (int i = 0; i < 4; i++) {
                float4 v = *(const float4*)(kp + i*4);
                v.x = tf32r(v.x); v.y = tf32r(v.y); v.z = tf32r(v.z); v.w = tf32r(v.w);
                *(float4*)&Ks[r*APAD + cb + i*4] = v;
                float4 u = *(const float4*)(vp + i*4);
                Vs[(cb + i*4 + 0)*APAD + r] = tf32r(u.x);
                Vs[(cb + i*4 + 1)*APAD + r] = tf32r(u.y);
                Vs[(cb + i*4 + 2)*APAD + r] = tf32r(u.z);
                Vs[(cb + i*4 + 3)*APAD + r] = tf32r(u.w);
            }
        }
        __syncthreads();

        // S = Q K^T  (warp 32q x 32keys)
        float sc[2][4][4];
        #pragma unroll
        for (int i = 0; i < 2; i++)
            #pragma unroll
            for (int j = 0; j < 4; j++)
                #pragma unroll
                for (int k = 0; k < 4; k++) sc[i][j][k] = 0.0f;
        #pragma unroll
        for (int ks = 0; ks < 8; ks++) {
            uint32_t af[2][4];
            #pragma unroll
            for (int mt = 0; mt < 2; mt++) {
                const int row = warpM*32 + mt*16 + g;
                const int base = row*APAD + ks*8 + t4;
                af[mt][0] = f2u(Qs[base]);
                af[mt][1] = f2u(Qs[base + 8*APAD]);
                af[mt][2] = f2u(Qs[base + 4]);
                af[mt][3] = f2u(Qs[base + 8*APAD + 4]);
            }
            uint32_t bf[4][2];
            #pragma unroll
            for (int nt = 0; nt < 4; nt++) {
                const int n = warpN*32 + nt*8 + g;
                const int bb = n*APAD + ks*8 + t4;
                bf[nt][0] = f2u(Ks[bb]);
                bf[nt][1] = f2u(Ks[bb + 4]);
            }
            #pragma unroll
            for (int mt = 0; mt < 2; mt++)
                #pragma unroll
                for (int nt = 0; nt < 4; nt++)
                    mma8(sc[mt][nt], af[mt], bf[nt]);
        }
        // store S to Ps
        #pragma unroll
        for (int mt = 0; mt < 2; mt++) {
            const int row = warpM*32 + mt*16 + g;
            #pragma unroll
            for (int nt = 0; nt < 4; nt++) {
                const int col = warpN*32 + nt*8 + 2*t4;
                *(float2*)&Ps[row*APAD + col] = make_float2(sc[mt][nt][0], sc[mt][nt][1]);
                *(float2*)&Ps[(row+8)*APAD + col] = make_float2(sc[mt][nt][2], sc[mt][nt][3]);
            }
        }
        __syncthreads();

        // online softmax on row srow, half shalf (32 cols)
        {
            float* pr = &Ps[srow*APAD + (shalf << 5)];
            float mx = -3.0e38f;
            #pragma unroll
            for (int j = 0; j < 8; j++) {
                float4 v = *(const float4*)(pr + j*4);
                mx = fmaxf(mx, fmaxf(fmaxf(v.x, v.y), fmaxf(v.z, v.w)));
            }
            mx = fmaxf(mx, __shfl_xor_sync(0xffffffffu, mx, 1));
            const float mnew = fmaxf(m_i, mx);
            const float corr = __expf(m_i - mnew);
            m_i = mnew;
            float sum = 0.0f;
            #pragma unroll
            for (int j = 0; j < 8; j++) {
                float4 v = *(const float4*)(pr + j*4);
                v.x = __expf(v.x - mnew); v.y = __expf(v.y - mnew);
                v.z = __expf(v.z - mnew); v.w = __expf(v.w - mnew);
                sum += v.x + v.y + v.z + v.w;
                v.x = tf32r(v.x); v.y = tf32r(v.y); v.z = tf32r(v.z); v.w = tf32r(v.w);
                *(float4*)(pr + j*4) = v;
            }
            sum += __shfl_xor_sync(0xffffffffu, sum, 1);
            l_i = l_i * corr + sum;
            if (!shalf) corr_s[srow] = corr;
        }
        __syncthreads();

        // rescale O, then O += P V   (warp 32q x 32d)
        {
            float cr[2][2];
            #pragma unroll
            for (int mt = 0; mt < 2; mt++) {
                const int row = warpM*32 + mt*16 + g;
                cr[mt][0] = corr_s[row];
                cr[mt][1] = corr_s[row + 8];
            }
            #pragma unroll
            for (int mt = 0; mt < 2; mt++)
                #pragma unroll
                for (int nt = 0; nt < 4; nt++) {
                    o[mt][nt][0] *= cr[mt][0]; o[mt][nt][1] *= cr[mt][0];
                    o[mt][nt][2] *= cr[mt][1]; o[mt][nt][3] *= cr[mt][1];
                }
            #pragma unroll
            for (int ks = 0; ks < 8; ks++) {
                uint32_t af[2][4];
                #pragma unroll
                for (int mt = 0; mt < 2; mt++) {
                    const int row = warpM*32 + mt*16 + g;
                    const int base = row*APAD + ks*8 + t4;
                    af[mt][0] = f2u(Ps[base]);
                    af[mt][1] = f2u(Ps[base + 8*APAD]);
                    af[mt][2] = f2u(Ps[base + 4]);
                    af[mt][3] = f2u(Ps[base + 8*APAD + 4]);
                }
                uint32_t bf[4][2];
                #pragma unroll
                for (int nt = 0; nt < 4; nt++) {
                    const int n = warpN*32 + nt*8 + g;   // d index
                    const int bb = n*APAD + ks*8 + t4;
                    bf[nt][0] = f2u(Vs[bb]);
                    bf[nt][1] = f2u(Vs[bb + 4]);
                }
                #pragma unroll
                for (int mt = 0; mt < 2; mt++)
                    #pragma unroll
                    for (int nt = 0; nt < 4; nt++)
                        mma8(o[mt][nt], af[mt], bf[nt]);
            }
        }
    }

    if (!shalf) l_s[srow] = l_i;
    __syncthreads();

    // epilogue: normalize, write ctx [b, s, h*64+d]
    #pragma unroll
    for (int mt = 0; mt < 2; mt++) {
        const int row = warpM*32 + mt*16 + g;
        const float inv0 = 1.0f / l_s[row];
        const float inv1 = 1.0f / l_s[row + 8];
        #pragma unroll
        for (int nt = 0; nt < 4; nt++) {
            const int d = warpN*32 + nt*8 + 2*t4;
            float* p = ctx + ((size_t)b * SS + q0 + row) * HID + h*DD + d;
            *(float2*)p = make_float2(o[mt][nt][0]*inv0, o[mt][nt][1]*inv0);
            *(float2*)(p + 8*HID) = make_float2(o[mt][nt][2]*inv1, o[mt][nt][3]*inv1);
        }
    }
}

// ---------------------------------------------------------------------------
extern "C" void kernel_launch(void* const* d_in, const int* in_sizes, int n_in,
                              void* d_out, int out_size)
{
    (void)in_sizes; (void)n_in; (void)out_size;
    const float* x  = (const float*)d_in[0];
    const float* Wq = (const float*)d_in[1];
    const float* bq = (const float*)d_in[2];
    const float* Wk = (const float*)d_in[3];
    const float* bk = (const float*)d_in[4];
    const float* Wv = (const float*)d_in[5];
    const float* bv = (const float*)d_in[6];
    const float* Wo = (const float*)d_in[7];
    const float* bo = (const float*)d_in[8];
    float* out = (float*)d_out;

    float *Qp, *Kp, *Vp, *Cp;
    cudaGetSymbolAddress((void**)&Qp, g_Q);
    cudaGetSymbolAddress((void**)&Kp, g_K);
    cudaGetSymbolAddress((void**)&Vp, g_V);
    cudaGetSymbolAddress((void**)&Cp, g_C);

    const int gemm_smem = (2*128*GPAD + 128) * 4;     // 37376
    const int attn_smem = 26368 * 4;                  // 105472
    cudaFuncSetAttribute(gemm_mma<0>, cudaFuncAttributeMaxDynamicSharedMemorySize, gemm_smem);
    cudaFuncSetAttribute(gemm_mma<1>, cudaFuncAttributeMaxDynamicSharedMemorySize, gemm_smem);
    cudaFuncSetAttribute(attn_mma,    cudaFuncAttributeMaxDynamicSharedMemorySize, attn_smem);

    dim3 ggrid(MT/128, HID/128);
    gemm_mma<1><<<ggrid, 256, gemm_smem>>>(x, Wq, bq, Qp);
    gemm_mma<1><<<ggrid, 256, gemm_smem>>>(x, Wk, bk, Kp);
    gemm_mma<1><<<ggrid, 256, gemm_smem>>>(x, Wv, bv, Vp);

    attn_mma<<<dim3(SS/128, HH, BB), 256, attn_smem>>>(Qp, Kp, Vp, Cp);

    gemm_mma<0><<<ggrid, 256, gemm_smem>>>(Cp, Wo, bo, out);
}

// round 5
// speedup vs baseline: 4.6925x; 1.3542x over previous
#include <cuda_runtime.h>
#include <cstdint>

// ---------------- problem constants ----------------
#define BB 4
#define SS 2048
#define HH 8
#define DD 64
#define HID 512
#define MT (BB*SS)   // 8192

// scratch
__device__ float g_Q[MT*HID];   // [b,h,s,d]  pre-scaled by 0.125*log2e, tf32-rounded
__device__ float g_K[MT*HID];   // [b,h,s,d]  tf32-rounded
__device__ float g_V[MT*HID];   // [b,h,s,d]  tf32-rounded
__device__ float g_C[MT*HID];   // ctx [b,s,hid] fp32

#define QSCALE 0.18033688011112042f   // 0.125 * log2(e)

__device__ __forceinline__ float tf32r(float x){
    float r; asm("cvt.rna.tf32.f32 %0, %1;" : "=f"(r) : "f"(x)); return r;
}
__device__ __forceinline__ float ex2(float x){
    float r; asm("ex2.approx.ftz.f32 %0, %1;" : "=f"(r) : "f"(x)); return r;
}
__device__ __forceinline__ uint32_t f2u(float x){ return __float_as_uint(x); }
__device__ __forceinline__ uint32_t smem_u32(const void* p){
    uint32_t a;
    asm("{ .reg .u64 t; cvta.to.shared.u64 t, %1; cvt.u32.u64 %0, t; }" : "=r"(a) : "l"(p));
    return a;
}
__device__ __forceinline__ void cpasync16(uint32_t dst, const void* src){
    asm volatile("cp.async.cg.shared.global [%0], [%1], 16;" :: "r"(dst), "l"(src) : "memory");
}
#define CP_COMMIT() asm volatile("cp.async.commit_group;" ::: "memory")
#define CP_WAIT0()  asm volatile("cp.async.wait_group 0;" ::: "memory")

// mma.sync m16n8k8 tf32: C(16x8) += A(16x8,row) * B(8x8,col)
__device__ __forceinline__ void mma8(float* c, const uint32_t* a, const uint32_t* b){
    asm volatile("mma.sync.aligned.m16n8k8.row.col.f32.tf32.tf32.f32 "
        "{%0,%1,%2,%3}, {%4,%5,%6,%7}, {%8,%9}, {%0,%1,%2,%3};"
        : "+f"(c[0]), "+f"(c[1]), "+f"(c[2]), "+f"(c[3])
        : "r"(a[0]), "r"(a[1]), "r"(a[2]), "r"(a[3]), "r"(b[0]), "r"(b[1]));
}

// ---------------------------------------------------------------------------
// GEMM: out = A[M,512] @ W[Nblk,512]^T + bias.  CTA tile 128x128, BK=32.
// 8 warps = 4(M) x 2(N).
// MODE 0: plain fp32 out[m][512]
// MODE 1: split-head [b,h,s,d], tf32-rounded (K, V)
// MODE 2: split-head [b,h,s,d], scaled by QSCALE then tf32-rounded (Q)
// ---------------------------------------------------------------------------
#define GPAD 36
template<int MODE>
__global__ __launch_bounds__(256, 2)
void gemm_mma(const float* __restrict__ A, const float* __restrict__ W,
              const float* __restrict__ bias, float* __restrict__ out)
{
    extern __shared__ float sm[];
    float* As = sm;                 // [128][36]
    float* Ws = sm + 128*GPAD;      // [128][36]
    float* bs = sm + 2*128*GPAD;    // [128]

    const int tid = threadIdx.x;
    const int lane = tid & 31, warp = tid >> 5;
    const int g = lane >> 2, t4 = lane & 3;
    const int warpM = warp >> 1, warpN = warp & 1;
    const int m0 = blockIdx.x << 7, n0 = blockIdx.y << 7;

    if (tid < 128) bs[tid] = bias[n0 + tid];

    float c[2][8][4];
    #pragma unroll
    for (int i = 0; i < 2; i++)
        #pragma unroll
        for (int j = 0; j < 8; j++)
            #pragma unroll
            for (int k = 0; k < 4; k++) c[i][j][k] = 0.0f;

    const int lr = tid >> 3;
    const int lc = (tid & 7) << 2;
    const float* Ap = A + (size_t)(m0 + lr) * HID + lc;
    const float* Wp = W + (size_t)(n0 + lr) * HID + lc;

    for (int k0 = 0; k0 < HID; k0 += 32) {
        #pragma unroll
        for (int i = 0; i < 4; i++) {
            float4 v = *(const float4*)(Ap + (size_t)i*32*HID + k0);
            v.x = tf32r(v.x); v.y = tf32r(v.y); v.z = tf32r(v.z); v.w = tf32r(v.w);
            *(float4*)&As[(lr + i*32)*GPAD + lc] = v;
            float4 u = *(const float4*)(Wp + (size_t)i*32*HID + k0);
            u.x = tf32r(u.x); u.y = tf32r(u.y); u.z = tf32r(u.z); u.w = tf32r(u.w);
            *(float4*)&Ws[(lr + i*32)*GPAD + lc] = u;
        }
        __syncthreads();
        #pragma unroll
        for (int ks = 0; ks < 4; ks++) {
            uint32_t af[2][4];
            #pragma unroll
            for (int mt = 0; mt < 2; mt++) {
                const int row = warpM*32 + mt*16 + g;
                const int base = row*GPAD + ks*8 + t4;
                af[mt][0] = f2u(As[base]);
                af[mt][1] = f2u(As[base + 8*GPAD]);
                af[mt][2] = f2u(As[base + 4]);
                af[mt][3] = f2u(As[base + 8*GPAD + 4]);
            }
            uint32_t bf[8][2];
            #pragma unroll
            for (int nt = 0; nt < 8; nt++) {
                const int n = warpN*64 + nt*8 + g;
                const int bb = n*GPAD + ks*8 + t4;
                bf[nt][0] = f2u(Ws[bb]);
                bf[nt][1] = f2u(Ws[bb + 4]);
            }
            #pragma unroll
            for (int mt = 0; mt < 2; mt++)
                #pragma unroll
                for (int nt = 0; nt < 8; nt++)
                    mma8(c[mt][nt], af[mt], bf[nt]);
        }
        __syncthreads();
    }

    #pragma unroll
    for (int mt = 0; mt < 2; mt++) {
        const int row = m0 + warpM*32 + mt*16 + g;
        #pragma unroll
        for (int nt = 0; nt < 8; nt++) {
            const int lcol = warpN*64 + nt*8 + 2*t4;
            const float b0 = bs[lcol], b1 = bs[lcol+1];
            float2 v0 = make_float2(c[mt][nt][0] + b0, c[mt][nt][1] + b1);
            float2 v1 = make_float2(c[mt][nt][2] + b0, c[mt][nt][3] + b1);
            if (MODE == 2) {
                v0.x *= QSCALE; v0.y *= QSCALE; v1.x *= QSCALE; v1.y *= QSCALE;
            }
            if (MODE >= 1) {
                v0.x = tf32r(v0.x); v0.y = tf32r(v0.y);
                v1.x = tf32r(v1.x); v1.y = tf32r(v1.y);
            }
            if (MODE == 0) {
                *(float2*)&out[(size_t)row * HID + n0 + lcol] = v0;
                *(float2*)&out[(size_t)(row+8) * HID + n0 + lcol] = v1;
            } else {
                const int bi = row >> 11, s = row & 2047;
                const int cg = n0 + lcol;
                const int h = cg >> 6, d = cg & 63;
                float* p = out + (((size_t)(bi*HH + h) * SS) + s) * DD + d;
                *(float2*)p = v0;
                *(float2*)(p + 8*DD) = v1;
            }
        }
    }
}

// ---------------------------------------------------------------------------
// Flash attention, register-resident FA2 on mma.sync tf32.
// 8 warps x 16 query rows; each warp covers all 64 keys / 64 d.
// Q fragments in registers (loaded once from pre-rounded g_Q).
// K/V tiles double-buffered via cp.async (pre-rounded in GEMM epilogue).
// Softmax + O-rescale fully in registers; P->A-fragment via shfl.
// K buffer stride 68 floats (bank=4g+t4), V stride 72 (bank=8t4+g): both
// conflict-free for their fragment load patterns.
// ---------------------------------------------------------------------------
#define KSTR 68
#define VSTR 72
#define KBUF_B (64*KSTR*4)   // 17408 bytes
#define VBUF_B (64*VSTR*4)   // 18432 bytes
// layout (bytes): K0=0, K1=17408, V0=34816, V1=53248; total 71680
__global__ __launch_bounds__(256, 2)
void attn_mma2(const float* __restrict__ Q, const float* __restrict__ K,
               const float* __restrict__ V, float* __restrict__ ctx)
{
    extern __shared__ float sm[];
    const uint32_t sb = smem_u32(sm);
    const int tid = threadIdx.x;
    const int lane = tid & 31, warp = tid >> 5;
    const int g = lane >> 2, t4 = lane & 3;
    const int b = blockIdx.z, h = blockIdx.y;
    const int q0 = blockIdx.x << 7;

    const float* Qg = Q + ((size_t)(b*HH + h) * SS + q0) * DD;
    const float* Kg = K + (size_t)(b*HH + h) * SS * DD;
    const float* Vg = V + (size_t)(b*HH + h) * SS * DD;

    // Q fragments: rows (16*warp+g) and (+8), 8 k-groups of 8
    uint32_t qf[8][4];
    {
        const uint32_t* q0p = (const uint32_t*)(Qg + (size_t)(warp*16 + g) * DD);
        const uint32_t* q1p = q0p + 8*DD;
        #pragma unroll
        for (int ks = 0; ks < 8; ks++) {
            qf[ks][0] = q0p[8*ks + t4];
            qf[ks][1] = q1p[8*ks + t4];
            qf[ks][2] = q0p[8*ks + t4 + 4];
            qf[ks][3] = q1p[8*ks + t4 + 4];
        }
    }

    // prologue: load tile 0 into buffer 0
    {
        #pragma unroll
        for (int i = 0; i < 4; i++) {
            const int cc = tid + i*256;
            const int row = cc >> 4, col = cc & 15;
            cpasync16(sb + row*(KSTR*4) + col*16, Kg + (size_t)row*DD + col*4);
            cpasync16(sb + 34816 + row*(VSTR*4) + col*16, Vg + (size_t)row*DD + col*4);
        }
        CP_COMMIT();
        CP_WAIT0();
    }
    __syncthreads();

    float o[8][4];
    #pragma unroll
    for (int j = 0; j < 8; j++)
        #pragma unroll
        for (int k = 0; k < 4; k++) o[j][k] = 0.0f;
    float m0r = -1.0e30f, m1r = -1.0e30f, l0r = 0.0f, l1r = 0.0f;

    #pragma unroll 1
    for (int t = 0; t < SS/64; t++) {
        const int cur = t & 1;
        const float* Ks = sm + cur * (KBUF_B/4);
        const float* Vs = sm + (34816/4) + cur * (VBUF_B/4);

        // prefetch next tile into the other buffer
        if (t < SS/64 - 1) {
            const uint32_t kd = sb + (cur^1) * KBUF_B;
            const uint32_t vd = sb + 34816 + (cur^1) * VBUF_B;
            const float* kn = Kg + (size_t)(t+1)*64*DD;
            const float* vn = Vg + (size_t)(t+1)*64*DD;
            #pragma unroll
            for (int i = 0; i < 4; i++) {
                const int cc = tid + i*256;
                const int row = cc >> 4, col = cc & 15;
                cpasync16(kd + row*(KSTR*4) + col*16, kn + (size_t)row*DD + col*4);
                cpasync16(vd + row*(VSTR*4) + col*16, vn + (size_t)row*DD + col*4);
            }
            CP_COMMIT();
        }

        // S = Q K^T  (16 x 64 per warp)
        float sc[8][4];
        #pragma unroll
        for (int j = 0; j < 8; j++)
            #pragma unroll
            for (int k = 0; k < 4; k++) sc[j][k] = 0.0f;
        #pragma unroll
        for (int ks = 0; ks < 8; ks++) {
            #pragma unroll
            for (int nt = 0; nt < 8; nt++) {
                const int bb = (8*nt + g)*KSTR + 8*ks + t4;
                uint32_t bf[2] = { f2u(Ks[bb]), f2u(Ks[bb + 4]) };
                mma8(sc[nt], qf[ks], bf);
            }
        }

        // online softmax (base-2 domain), rows g and g+8
        float mx0 = -1.0e30f, mx1 = -1.0e30f;
        #pragma unroll
        for (int nt = 0; nt < 8; nt++) {
            mx0 = fmaxf(mx0, fmaxf(sc[nt][0], sc[nt][1]));
            mx1 = fmaxf(mx1, fmaxf(sc[nt][2], sc[nt][3]));
        }
        mx0 = fmaxf(mx0, __shfl_xor_sync(0xffffffffu, mx0, 1));
        mx0 = fmaxf(mx0, __shfl_xor_sync(0xffffffffu, mx0, 2));
        mx1 = fmaxf(mx1, __shfl_xor_sync(0xffffffffu, mx1, 1));
        mx1 = fmaxf(mx1, __shfl_xor_sync(0xffffffffu, mx1, 2));
        const float mn0 = fmaxf(m0r, mx0), mn1 = fmaxf(m1r, mx1);
        const float corr0 = ex2(m0r - mn0), corr1 = ex2(m1r - mn1);
        m0r = mn0; m1r = mn1;
        float sum0 = 0.0f, sum1 = 0.0f;
        #pragma unroll
        for (int nt = 0; nt < 8; nt++) {
            float p0 = ex2(sc[nt][0] - mn0);
            float p1 = ex2(sc[nt][1] - mn0);
            float p2 = ex2(sc[nt][2] - mn1);
            float p3 = ex2(sc[nt][3] - mn1);
            sum0 += p0 + p1; sum1 += p2 + p3;
            sc[nt][0] = tf32r(p0); sc[nt][1] = tf32r(p1);
            sc[nt][2] = tf32r(p2); sc[nt][3] = tf32r(p3);
        }
        sum0 += __shfl_xor_sync(0xffffffffu, sum0, 1);
        sum0 += __shfl_xor_sync(0xffffffffu, sum0, 2);
        sum1 += __shfl_xor_sync(0xffffffffu, sum1, 1);
        sum1 += __shfl_xor_sync(0xffffffffu, sum1, 2);
        l0r = l0r * corr0 + sum0;
        l1r = l1r * corr1 + sum1;

        // rescale O
        #pragma unroll
        for (int nt = 0; nt < 8; nt++) {
            o[nt][0] *= corr0; o[nt][1] *= corr0;
            o[nt][2] *= corr1; o[nt][3] *= corr1;
        }

        // PV: O += P V.  A-fragments of P built via shfl from accumulators.
        const int s0l = (lane & 28) | (t4 >> 1);
        const int s2l = s0l + 2;
        const bool odd = (t4 & 1);
        #pragma unroll
        for (int ks = 0; ks < 8; ks++) {
            const float v00 = __shfl_sync(0xffffffffu, sc[ks][0], s0l);
            const float v10 = __shfl_sync(0xffffffffu, sc[ks][1], s0l);
            const float v02 = __shfl_sync(0xffffffffu, sc[ks][0], s2l);
            const float v12 = __shfl_sync(0xffffffffu, sc[ks][1], s2l);
            const float v20 = __shfl_sync(0xffffffffu, sc[ks][2], s0l);
            const float v30 = __shfl_sync(0xffffffffu, sc[ks][3], s0l);
            const float v22 = __shfl_sync(0xffffffffu, sc[ks][2], s2l);
            const float v32 = __shfl_sync(0xffffffffu, sc[ks][3], s2l);
            uint32_t af[4];
            af[0] = f2u(odd ? v10 : v00);
            af[1] = f2u(odd ? v30 : v20);
            af[2] = f2u(odd ? v12 : v02);
            af[3] = f2u(odd ? v32 : v22);
            #pragma unroll
            for (int nt = 0; nt < 8; nt++) {
                const int bb = (8*ks + t4)*VSTR + 8*nt + g;
                uint32_t bf[2] = { f2u(Vs[bb]), f2u(Vs[bb + 4*VSTR]) };
                mma8(o[nt], af, bf);
            }
        }

        CP_WAIT0();
        __syncthreads();
    }

    // epilogue
    const float inv0 = 1.0f / l0r, inv1 = 1.0f / l1r;
    const int row = q0 + warp*16 + g;
    #pragma unroll
    for (int nt = 0; nt < 8; nt++) {
        const int d = 8*nt + 2*t4;
        float* p = ctx + ((size_t)b * SS + row) * HID + h*DD + d;
        *(float2*)p = make_float2(o[nt][0]*inv0, o[nt][1]*inv0);
        *(float2*)(p + 8*HID) = make_float2(o[nt][2]*inv1, o[nt][3]*inv1);
    }
}

// ---------------------------------------------------------------------------
extern "C" void kernel_launch(void* const* d_in, const int* in_sizes, int n_in,
                              void* d_out, int out_size)
{
    (void)in_sizes; (void)n_in; (void)out_size;
    const float* x  = (const float*)d_in[0];
    const float* Wq = (const float*)d_in[1];
    const float* bq = (const float*)d_in[2];
    const float* Wk = (const float*)d_in[3];
    const float* bk = (const float*)d_in[4];
    const float* Wv = (const float*)d_in[5];
    const float* bv = (const float*)d_in[6];
    const float* Wo = (const float*)d_in[7];
    const float* bo = (const float*)d_in[8];
    float* out = (float*)d_out;

    float *Qp, *Kp, *Vp, *Cp;
    cudaGetSymbolAddress((void**)&Qp, g_Q);
    cudaGetSymbolAddress((void**)&Kp, g_K);
    cudaGetSymbolAddress((void**)&Vp, g_V);
    cudaGetSymbolAddress((void**)&Cp, g_C);

    const int gemm_smem = (2*128*GPAD + 128) * 4;   // 37376
    const int attn_smem = 71680;
    cudaFuncSetAttribute(gemm_mma<0>, cudaFuncAttributeMaxDynamicSharedMemorySize, gemm_smem);
    cudaFuncSetAttribute(gemm_mma<1>, cudaFuncAttributeMaxDynamicSharedMemorySize, gemm_smem);
    cudaFuncSetAttribute(gemm_mma<2>, cudaFuncAttributeMaxDynamicSharedMemorySize, gemm_smem);
    cudaFuncSetAttribute(attn_mma2,   cudaFuncAttributeMaxDynamicSharedMemorySize, attn_smem);

    dim3 ggrid(MT/128, HID/128);
    gemm_mma<2><<<ggrid, 256, gemm_smem>>>(x, Wq, bq, Qp);   // Q: scaled+rounded
    gemm_mma<1><<<ggrid, 256, gemm_smem>>>(x, Wk, bk, Kp);   // K: rounded
    gemm_mma<1><<<ggrid, 256, gemm_smem>>>(x, Wv, bv, Vp);   // V: rounded

    attn_mma2<<<dim3(SS/128, HH, BB), 256, attn_smem>>>(Qp, Kp, Vp, Cp);

    gemm_mma<0><<<ggrid, 256, gemm_smem>>>(Cp, Wo, bo, out);
}

// round 6
// speedup vs baseline: 5.4093x; 1.1528x over previous
#include <cuda_runtime.h>
#include <cstdint>

// ---------------- problem constants ----------------
#define BB 4
#define SS 2048
#define HH 8
#define DD 64
#define HID 512
#define MT (BB*SS)   // 8192

// scratch
__device__ float g_Q[MT*HID];   // [b,h,s,d]  pre-scaled by 0.125*log2e, tf32-rounded
__device__ float g_K[MT*HID];   // [b,h,s,d]  tf32-rounded
__device__ float g_V[MT*HID];   // [b,h,d,s]  TRANSPOSED, tf32-rounded
__device__ float g_C[MT*HID];   // ctx [b,s,hid] fp32

#define QSCALE 0.18033688011112042f   // 0.125 * log2(e)

__device__ __forceinline__ float tf32r(float x){
    float r; asm("cvt.rna.tf32.f32 %0, %1;" : "=f"(r) : "f"(x)); return r;
}
__device__ __forceinline__ float ex2(float x){
    float r; asm("ex2.approx.ftz.f32 %0, %1;" : "=f"(r) : "f"(x)); return r;
}
__device__ __forceinline__ uint32_t f2u(float x){ return __float_as_uint(x); }
__device__ __forceinline__ uint32_t smem_u32(const void* p){
    uint32_t a;
    asm("{ .reg .u64 t; cvta.to.shared.u64 t, %1; cvt.u32.u64 %0, t; }" : "=r"(a) : "l"(p));
    return a;
}
__device__ __forceinline__ void cpasync16(uint32_t dst, const void* src){
    asm volatile("cp.async.cg.shared.global [%0], [%1], 16;" :: "r"(dst), "l"(src) : "memory");
}
#define CP_COMMIT() asm volatile("cp.async.commit_group;" ::: "memory")
#define CP_WAIT0()  asm volatile("cp.async.wait_group 0;" ::: "memory")

// mma.sync m16n8k8 tf32
__device__ __forceinline__ void mma8(float* c, const uint32_t* a, const uint32_t* b){
    asm volatile("mma.sync.aligned.m16n8k8.row.col.f32.tf32.tf32.f32 "
        "{%0,%1,%2,%3}, {%4,%5,%6,%7}, {%8,%9}, {%0,%1,%2,%3};"
        : "+f"(c[0]), "+f"(c[1]), "+f"(c[2]), "+f"(c[3])
        : "r"(a[0]), "r"(a[1]), "r"(a[2]), "r"(a[3]), "r"(b[0]), "r"(b[1]));
}
// ldmatrix x4 (b16 view of 32-bit data -> tf32 fragment quad layout)
__device__ __forceinline__ void ldsm4(uint32_t* r, uint32_t addr){
    asm volatile("ldmatrix.sync.aligned.m8n8.x4.shared.b16 {%0,%1,%2,%3}, [%4];"
        : "=r"(r[0]), "=r"(r[1]), "=r"(r[2]), "=r"(r[3]) : "r"(addr));
}

// ---------------------------------------------------------------------------
// GEMM core: out = A[M,512] @ W[Nblk,512]^T + bias.  CTA 128x128, BK=32,
// 8 warps = 4(M) x 2(N).  Double-buffered smem (reg prefetch, rna at STS),
// ldmatrix fragments.  Stride 36 floats = 144B (16 mod 128 -> LDSM clean).
// MODE 0: fp32 [m][512]   MODE 1: [b,h,s,d] rna   MODE 2: Q scaled+rna
// MODE 3: V^T [b,h,d,s] rna
// ---------------------------------------------------------------------------
#define GPAD 36
#define GSTR_B 144
#define GBUF_F (128*GPAD)       // floats per matrix per stage (4608)

template<int MODE>
__device__ __forceinline__ void gemm_core(
    const float* __restrict__ A, const float* __restrict__ W,
    const float* __restrict__ bias, float* __restrict__ out,
    float* sm, int m0, int n0)
{
    // layout: As0 Ws0 As1 Ws1 bias
    float* bs = sm + 4*GBUF_F;
    const uint32_t sb = smem_u32(sm);

    const int tid = threadIdx.x;
    const int lane = tid & 31, warp = tid >> 5;
    const int g = lane >> 2, t4 = lane & 3;
    const int warpM = warp >> 1, warpN = warp & 1;
    const int lm = lane >> 3, lr8 = lane & 7;
    // A-frag lane offset: matrix m -> rows (m&1)*8, colhalf m>>1
    const uint32_t laneA = ((uint32_t)((lm & 1)*8 + lr8))*GSTR_B + (uint32_t)(lm >> 1)*16;
    // B-frag lane offset: matrix m -> rows (m>>1)*8, colhalf m&1
    const uint32_t laneB = ((uint32_t)((lm >> 1)*8 + lr8))*GSTR_B + (uint32_t)(lm & 1)*16;

    if (tid < 128) bs[tid] = bias[n0 + tid];

    float c[2][8][4];
    #pragma unroll
    for (int i = 0; i < 2; i++)
        #pragma unroll
        for (int j = 0; j < 8; j++)
            #pragma unroll
            for (int k = 0; k < 4; k++) c[i][j][k] = 0.0f;

    const int lrow = tid >> 3;          // 0..31
    const int lcol = (tid & 7) << 2;    // 0..28
    const float* Ap = A + (size_t)(m0 + lrow) * HID + lcol;
    const float* Wp = W + (size_t)(n0 + lrow) * HID + lcol;

    float4 av[4], uv[4];
    // prologue: chunk 0 -> buf 0
    #pragma unroll
    for (int i = 0; i < 4; i++) {
        av[i] = *(const float4*)(Ap + (size_t)i*32*HID);
        uv[i] = *(const float4*)(Wp + (size_t)i*32*HID);
    }
    #pragma unroll
    for (int i = 0; i < 4; i++) {
        float4 v = av[i];
        v.x = tf32r(v.x); v.y = tf32r(v.y); v.z = tf32r(v.z); v.w = tf32r(v.w);
        *(float4*)&sm[(lrow + i*32)*GPAD + lcol] = v;
        float4 u = uv[i];
        u.x = tf32r(u.x); u.y = tf32r(u.y); u.z = tf32r(u.z); u.w = tf32r(u.w);
        *(float4*)&sm[GBUF_F + (lrow + i*32)*GPAD + lcol] = u;
    }
    __syncthreads();

    #pragma unroll 1
    for (int ch = 0; ch < 16; ch++) {
        const int cur = ch & 1;
        if (ch < 15) {
            #pragma unroll
            for (int i = 0; i < 4; i++) {
                av[i] = *(const float4*)(Ap + (size_t)i*32*HID + (ch+1)*32);
                uv[i] = *(const float4*)(Wp + (size_t)i*32*HID + (ch+1)*32);
            }
        }
        const uint32_t abase = sb + cur*(2*GBUF_F*4) + (uint32_t)(warpM*32)*GSTR_B + laneA;
        const uint32_t bbase = sb + cur*(2*GBUF_F*4) + GBUF_F*4 + (uint32_t)(warpN*64)*GSTR_B + laneB;
        #pragma unroll
        for (int ks = 0; ks < 4; ks++) {
            uint32_t af[2][4];
            ldsm4(af[0], abase + ks*32);
            ldsm4(af[1], abase + 16*GSTR_B + ks*32);
            #pragma unroll
            for (int p = 0; p < 4; p++) {
                uint32_t bf[4];
                ldsm4(bf, bbase + (uint32_t)(p*16)*GSTR_B + ks*32);
                mma8(c[0][2*p],   af[0], bf);
                mma8(c[0][2*p+1], af[0], bf+2);
                mma8(c[1][2*p],   af[1], bf);
                mma8(c[1][2*p+1], af[1], bf+2);
            }
        }
        if (ch < 15) {
            float* dst = sm + (cur^1)*(2*GBUF_F);
            #pragma unroll
            for (int i = 0; i < 4; i++) {
                float4 v = av[i];
                v.x = tf32r(v.x); v.y = tf32r(v.y); v.z = tf32r(v.z); v.w = tf32r(v.w);
                *(float4*)&dst[(lrow + i*32)*GPAD + lcol] = v;
                float4 u = uv[i];
                u.x = tf32r(u.x); u.y = tf32r(u.y); u.z = tf32r(u.z); u.w = tf32r(u.w);
                *(float4*)&dst[GBUF_F + (lrow + i*32)*GPAD + lcol] = u;
            }
        }
        __syncthreads();
    }

    // epilogue
    #pragma unroll
    for (int mt = 0; mt < 2; mt++) {
        const int row = m0 + warpM*32 + mt*16 + g;
        #pragma unroll
        for (int nt = 0; nt < 8; nt++) {
            const int lc2 = warpN*64 + nt*8 + 2*t4;
            const float b0 = bs[lc2], b1 = bs[lc2+1];
            float2 v0 = make_float2(c[mt][nt][0] + b0, c[mt][nt][1] + b1);
            float2 v1 = make_float2(c[mt][nt][2] + b0, c[mt][nt][3] + b1);
            if (MODE == 2) { v0.x *= QSCALE; v0.y *= QSCALE; v1.x *= QSCALE; v1.y *= QSCALE; }
            if (MODE >= 1) {
                v0.x = tf32r(v0.x); v0.y = tf32r(v0.y);
                v1.x = tf32r(v1.x); v1.y = tf32r(v1.y);
            }
            if (MODE == 0) {
                *(float2*)&out[(size_t)row * HID + n0 + lc2] = v0;
                *(float2*)&out[(size_t)(row+8) * HID + n0 + lc2] = v1;
            } else if (MODE == 3) {
                const int bi = row >> 11, s = row & 2047;
                const int cg = n0 + lc2;
                const int h = cg >> 6, d = cg & 63;
                float* p = out + ((size_t)(bi*HH + h) * DD + d) * SS + s;
                p[0] = v0.x; p[SS] = v0.y;
                p[8] = v1.x; p[SS + 8] = v1.y;
            } else {
                const int bi = row >> 11, s = row & 2047;
                const int cg = n0 + lc2;
                const int h = cg >> 6, d = cg & 63;
                float* p = out + (((size_t)(bi*HH + h) * SS) + s) * DD + d;
                *(float2*)p = v0;
                *(float2*)(p + 8*DD) = v1;
            }
        }
    }
}

// fused QKV projection: grid.z selects matrix
__global__ __launch_bounds__(256, 2)
void gemm_qkv(const float* __restrict__ x,
              const float* __restrict__ Wq, const float* __restrict__ bq,
              const float* __restrict__ Wk, const float* __restrict__ bk,
              const float* __restrict__ Wv, const float* __restrict__ bv,
              float* __restrict__ Qp, float* __restrict__ Kp, float* __restrict__ Vp)
{
    extern __shared__ float sm[];
    const int m0 = blockIdx.x << 7, n0 = blockIdx.y << 7;
    if (blockIdx.z == 0)      gemm_core<2>(x, Wq, bq, Qp, sm, m0, n0);
    else if (blockIdx.z == 1) gemm_core<1>(x, Wk, bk, Kp, sm, m0, n0);
    else                      gemm_core<3>(x, Wv, bv, Vp, sm, m0, n0);
}

__global__ __launch_bounds__(256, 2)
void gemm_out(const float* __restrict__ A, const float* __restrict__ W,
              const float* __restrict__ bias, float* __restrict__ out)
{
    extern __shared__ float sm[];
    gemm_core<0>(A, W, bias, out, sm, blockIdx.x << 7, blockIdx.y << 7);
}

// ---------------------------------------------------------------------------
// Flash attention: register FA2, ldmatrix fragments, cp.async double buffer.
// 8 warps x 16 query rows.  K smem [key][d] stride 68; V smem [d][key]
// stride 68 (from transposed g_V).  272B row stride -> LDSM conflict-free.
// ---------------------------------------------------------------------------
#define ASTR_B 272                // 68 floats
#define KBUF_B (64*ASTR_B)        // 17408
// bytes: K0=0, K1=17408, V0=34816, V1=52224; total 69632
__global__ __launch_bounds__(256, 2)
void attn_mma3(const float* __restrict__ Q, const float* __restrict__ K,
               const float* __restrict__ Vt, float* __restrict__ ctx)
{
    extern __shared__ float sm[];
    const uint32_t sb = smem_u32(sm);
    const int tid = threadIdx.x;
    const int lane = tid & 31, warp = tid >> 5;
    const int g = lane >> 2, t4 = lane & 3;
    const int lm = lane >> 3, lr8 = lane & 7;
    const uint32_t laneB = ((uint32_t)((lm >> 1)*8 + lr8))*ASTR_B + (uint32_t)(lm & 1)*16;
    const int b = blockIdx.z, h = blockIdx.y;
    const int q0 = blockIdx.x << 7;

    const float* Qg = Q  + ((size_t)(b*HH + h) * SS + q0) * DD;
    const float* Kg = K  + (size_t)(b*HH + h) * SS * DD;
    const float* Vg = Vt + (size_t)(b*HH + h) * DD * SS;   // [d][s]

    // Q fragments (rows 16*warp+g, +8)
    uint32_t qf[8][4];
    {
        const uint32_t* q0p = (const uint32_t*)(Qg + (size_t)(warp*16 + g) * DD);
        const uint32_t* q1p = q0p + 8*DD;
        #pragma unroll
        for (int ks = 0; ks < 8; ks++) {
            qf[ks][0] = q0p[8*ks + t4];
            qf[ks][1] = q1p[8*ks + t4];
            qf[ks][2] = q0p[8*ks + t4 + 4];
            qf[ks][3] = q1p[8*ks + t4 + 4];
        }
    }

    // prologue: tile 0 -> buffer 0
    {
        #pragma unroll
        for (int i = 0; i < 4; i++) {
            const int cc = tid + i*256;
            const int row = cc >> 4, col = cc & 15;
            cpasync16(sb + row*ASTR_B + col*16, Kg + (size_t)row*DD + col*4);
            cpasync16(sb + 34816 + row*ASTR_B + col*16, Vg + (size_t)row*SS + col*4);
        }
        CP_COMMIT();
        CP_WAIT0();
    }
    __syncthreads();

    float o[8][4];
    #pragma unroll
    for (int j = 0; j < 8; j++)
        #pragma unroll
        for (int k = 0; k < 4; k++) o[j][k] = 0.0f;
    float m0r = -1.0e30f, m1r = -1.0e30f, l0r = 0.0f, l1r = 0.0f;

    #pragma unroll 1
    for (int t = 0; t < SS/64; t++) {
        const int cur = t & 1;
        const uint32_t kbase = sb + cur*KBUF_B + laneB;
        const uint32_t vbase = sb + 34816 + cur*KBUF_B + laneB;

        if (t < SS/64 - 1) {
            const uint32_t kd = sb + (cur^1)*KBUF_B;
            const uint32_t vd = sb + 34816 + (cur^1)*KBUF_B;
            const float* kn = Kg + (size_t)(t+1)*64*DD;
            const float* vn = Vg + (t+1)*64;
            #pragma unroll
            for (int i = 0; i < 4; i++) {
                const int cc = tid + i*256;
                const int row = cc >> 4, col = cc & 15;
                cpasync16(kd + row*ASTR_B + col*16, kn + (size_t)row*DD + col*4);
                cpasync16(vd + row*ASTR_B + col*16, vn + (size_t)row*SS + col*4);
            }
            CP_COMMIT();
        }

        // S = Q K^T
        float sc[8][4];
        #pragma unroll
        for (int j = 0; j < 8; j++)
            #pragma unroll
            for (int k = 0; k < 4; k++) sc[j][k] = 0.0f;
        #pragma unroll
        for (int ks = 0; ks < 8; ks++) {
            #pragma unroll
            for (int p = 0; p < 4; p++) {
                uint32_t bf[4];
                ldsm4(bf, kbase + (uint32_t)(p*16)*ASTR_B + ks*32);
                mma8(sc[2*p],   qf[ks], bf);
                mma8(sc[2*p+1], qf[ks], bf+2);
            }
        }

        // online softmax (base-2), rows g and g+8
        float mx0 = -1.0e30f, mx1 = -1.0e30f;
        #pragma unroll
        for (int nt = 0; nt < 8; nt++) {
            mx0 = fmaxf(mx0, fmaxf(sc[nt][0], sc[nt][1]));
            mx1 = fmaxf(mx1, fmaxf(sc[nt][2], sc[nt][3]));
        }
        mx0 = fmaxf(mx0, __shfl_xor_sync(0xffffffffu, mx0, 1));
        mx0 = fmaxf(mx0, __shfl_xor_sync(0xffffffffu, mx0, 2));
        mx1 = fmaxf(mx1, __shfl_xor_sync(0xffffffffu, mx1, 1));
        mx1 = fmaxf(mx1, __shfl_xor_sync(0xffffffffu, mx1, 2));
        const float mn0 = fmaxf(m0r, mx0), mn1 = fmaxf(m1r, mx1);
        const float corr0 = ex2(m0r - mn0), corr1 = ex2(m1r - mn1);
        m0r = mn0; m1r = mn1;
        float sum0 = 0.0f, sum1 = 0.0f;
        #pragma unroll
        for (int nt = 0; nt < 8; nt++) {
            float p0 = ex2(sc[nt][0] - mn0);
            float p1 = ex2(sc[nt][1] - mn0);
            float p2 = ex2(sc[nt][2] - mn1);
            float p3 = ex2(sc[nt][3] - mn1);
            sum0 += p0 + p1; sum1 += p2 + p3;
            sc[nt][0] = tf32r(p0); sc[nt][1] = tf32r(p1);
            sc[nt][2] = tf32r(p2); sc[nt][3] = tf32r(p3);
        }
        sum0 += __shfl_xor_sync(0xffffffffu, sum0, 1);
        sum0 += __shfl_xor_sync(0xffffffffu, sum0, 2);
        sum1 += __shfl_xor_sync(0xffffffffu, sum1, 1);
        sum1 += __shfl_xor_sync(0xffffffffu, sum1, 2);
        l0r = l0r * corr0 + sum0;
        l1r = l1r * corr1 + sum1;

        #pragma unroll
        for (int nt = 0; nt < 8; nt++) {
            o[nt][0] *= corr0; o[nt][1] *= corr0;
            o[nt][2] *= corr1; o[nt][3] *= corr1;
        }

        // PV: O += P V   (A-frags of P via shfl; B-frags of V via ldmatrix)
        const int s0l = (lane & 28) | (t4 >> 1);
        const int s2l = s0l + 2;
        const bool odd = (t4 & 1);
        #pragma unroll
        for (int ks = 0; ks < 8; ks++) {
            const float v00 = __shfl_sync(0xffffffffu, sc[ks][0], s0l);
            const float v10 = __shfl_sync(0xffffffffu, sc[ks][1], s0l);
            const float v02 = __shfl_sync(0xffffffffu, sc[ks][0], s2l);
            const float v12 = __shfl_sync(0xffffffffu, sc[ks][1], s2l);
            const float v20 = __shfl_sync(0xffffffffu, sc[ks][2], s0l);
            const float v30 = __shfl_sync(0xffffffffu, sc[ks][3], s0l);
            const float v22 = __shfl_sync(0xffffffffu, sc[ks][2], s2l);
            const float v32 = __shfl_sync(0xffffffffu, sc[ks][3], s2l);
            uint32_t af[4];
            af[0] = f2u(odd ? v10 : v00);
            af[1] = f2u(odd ? v30 : v20);
            af[2] = f2u(odd ? v12 : v02);
            af[3] = f2u(odd ? v32 : v22);
            #pragma unroll
            for (int p = 0; p < 4; p++) {
                uint32_t bf[4];
                ldsm4(bf, vbase + (uint32_t)(p*16)*ASTR_B + ks*32);
                mma8(o[2*p],   af, bf);
                mma8(o[2*p+1], af, bf+2);
            }
        }

        CP_WAIT0();
        __syncthreads();
    }

    // epilogue
    const float inv0 = 1.0f / l0r, inv1 = 1.0f / l1r;
    const int row = q0 + warp*16 + g;
    #pragma unroll
    for (int nt = 0; nt < 8; nt++) {
        const int d = 8*nt + 2*t4;
        float* p = ctx + ((size_t)b * SS + row) * HID + h*DD + d;
        *(float2*)p = make_float2(o[nt][0]*inv0, o[nt][1]*inv0);
        *(float2*)(p + 8*HID) = make_float2(o[nt][2]*inv1, o[nt][3]*inv1);
    }
}

// ---------------------------------------------------------------------------
extern "C" void kernel_launch(void* const* d_in, const int* in_sizes, int n_in,
                              void* d_out, int out_size)
{
    (void)in_sizes; (void)n_in; (void)out_size;
    const float* x  = (const float*)d_in[0];
    const float* Wq = (const float*)d_in[1];
    const float* bq = (const float*)d_in[2];
    const float* Wk = (const float*)d_in[3];
    const float* bk = (const float*)d_in[4];
    const float* Wv = (const float*)d_in[5];
    const float* bv = (const float*)d_in[6];
    const float* Wo = (const float*)d_in[7];
    const float* bo = (const float*)d_in[8];
    float* out = (float*)d_out;

    float *Qp, *Kp, *Vp, *Cp;
    cudaGetSymbolAddress((void**)&Qp, g_Q);
    cudaGetSymbolAddress((void**)&Kp, g_K);
    cudaGetSymbolAddress((void**)&Vp, g_V);
    cudaGetSymbolAddress((void**)&Cp, g_C);

    const int gemm_smem = (4*GBUF_F + 128) * 4;   // 74240
    const int attn_smem = 69632;
    cudaFuncSetAttribute(gemm_qkv, cudaFuncAttributeMaxDynamicSharedMemorySize, gemm_smem);
    cudaFuncSetAttribute(gemm_out, cudaFuncAttributeMaxDynamicSharedMemorySize, gemm_smem);
    cudaFuncSetAttribute(attn_mma3, cudaFuncAttributeMaxDynamicSharedMemorySize, attn_smem);

    gemm_qkv<<<dim3(MT/128, HID/128, 3), 256, gemm_smem>>>(
        x, Wq, bq, Wk, bk, Wv, bv, Qp, Kp, Vp);

    attn_mma3<<<dim3(SS/128, HH, BB), 256, attn_smem>>>(Qp, Kp, Vp, Cp);

    gemm_out<<<dim3(MT/128, HID/128), 256, gemm_smem>>>(Cp, Wo, bo, out);
}

// round 8
// speedup vs baseline: 6.8120x; 1.2593x over previous
#include <cuda_runtime.h>
#include <cuda_fp16.h>
#include <cstdint>

// ---------------- problem constants ----------------
#define BB 4
#define SS 2048
#define HH 8
#define DD 64
#define HID 512
#define MT (BB*SS)   // 8192

// scratch
__device__ float g_Q[MT*HID];      // [b,h,s,d]  pre-scaled by 0.125*log2e, tf32-rounded
__device__ float g_K[MT*HID];      // [b,h,s,d]  tf32-rounded
__device__ __half g_V[MT*HID];     // [b,h,s,d]  fp16 (rn)
__device__ float g_C[MT*HID];      // ctx [b,s,hid] fp32

#define QSCALE 0.18033688011112042f   // 0.125 * log2(e)

__device__ __forceinline__ float tf32r(float x){
    float r; asm("cvt.rna.tf32.f32 %0, %1;" : "=f"(r) : "f"(x)); return r;
}
__device__ __forceinline__ float ex2(float x){
    float r; asm("ex2.approx.ftz.f32 %0, %1;" : "=f"(r) : "f"(x)); return r;
}
__device__ __forceinline__ uint32_t f2u(float x){ return __float_as_uint(x); }
// pack {lo, hi} floats into f16x2 (round-to-nearest)
__device__ __forceinline__ uint32_t pkhf(float lo, float hi){
    uint32_t d; asm("cvt.rn.f16x2.f32 %0, %1, %2;" : "=r"(d) : "f"(hi), "f"(lo)); return d;
}
__device__ __forceinline__ uint32_t smem_u32(const void* p){
    uint32_t a;
    asm("{ .reg .u64 t; cvta.to.shared.u64 t, %1; cvt.u32.u64 %0, t; }" : "=r"(a) : "l"(p));
    return a;
}
__device__ __forceinline__ void cpasync16(uint32_t dst, const void* src){
    asm volatile("cp.async.cg.shared.global [%0], [%1], 16;" :: "r"(dst), "l"(src) : "memory");
}
#define CP_COMMIT() asm volatile("cp.async.commit_group;" ::: "memory")
#define CP_WAIT0()  asm volatile("cp.async.wait_group 0;" ::: "memory")

// mma.sync m16n8k8 tf32
__device__ __forceinline__ void mma8(float* c, const uint32_t* a, const uint32_t* b){
    asm volatile("mma.sync.aligned.m16n8k8.row.col.f32.tf32.tf32.f32 "
        "{%0,%1,%2,%3}, {%4,%5,%6,%7}, {%8,%9}, {%0,%1,%2,%3};"
        : "+f"(c[0]), "+f"(c[1]), "+f"(c[2]), "+f"(c[3])
        : "r"(a[0]), "r"(a[1]), "r"(a[2]), "r"(a[3]), "r"(b[0]), "r"(b[1]));
}
// mma.sync m16n8k16 f16 (fp32 accumulate)
__device__ __forceinline__ void mma16(float* c, const uint32_t* a, const uint32_t* b){
    asm volatile("mma.sync.aligned.m16n8k16.row.col.f32.f16.f16.f32 "
        "{%0,%1,%2,%3}, {%4,%5,%6,%7}, {%8,%9}, {%0,%1,%2,%3};"
        : "+f"(c[0]), "+f"(c[1]), "+f"(c[2]), "+f"(c[3])
        : "r"(a[0]), "r"(a[1]), "r"(a[2]), "r"(a[3]), "r"(b[0]), "r"(b[1]));
}
// ldmatrix x4 (b16 view)
__device__ __forceinline__ void ldsm4(uint32_t* r, uint32_t addr){
    asm volatile("ldmatrix.sync.aligned.m8n8.x4.shared.b16 {%0,%1,%2,%3}, [%4];"
        : "=r"(r[0]), "=r"(r[1]), "=r"(r[2]), "=r"(r[3]) : "r"(addr));
}
// ldmatrix x4 transposed (16-bit elements)
__device__ __forceinline__ void ldsm4t(uint32_t* r, uint32_t addr){
    asm volatile("ldmatrix.sync.aligned.m8n8.x4.trans.shared.b16 {%0,%1,%2,%3}, [%4];"
        : "=r"(r[0]), "=r"(r[1]), "=r"(r[2]), "=r"(r[3]) : "r"(addr));
}

// ---------------------------------------------------------------------------
// GEMM core: out = A[M,512] @ W[Nblk,512]^T + bias.  CTA 128x128, BK=32,
// 8 warps = 4(M) x 2(N).  Double-buffered smem, ldmatrix fragments.
// MODE 0: fp32 [m][512]   MODE 1: [b,h,s,d] rna   MODE 2: Q scaled+rna
// MODE 3: V fp16 [b,h,s,d] rn
// ---------------------------------------------------------------------------
#define GPAD 36
#define GSTR_B 144
#define GBUF_F (128*GPAD)       // floats per matrix per stage (4608)

template<int MODE>
__device__ __forceinline__ void gemm_core(
    const float* __restrict__ A, const float* __restrict__ W,
    const float* __restrict__ bias, void* __restrict__ outv,
    float* sm, int m0, int n0)
{
    float* bs = sm + 4*GBUF_F;
    const uint32_t sb = smem_u32(sm);

    const int tid = threadIdx.x;
    const int lane = tid & 31, warp = tid >> 5;
    const int g = lane >> 2, t4 = lane & 3;
    const int warpM = warp >> 1, warpN = warp & 1;
    const int lm = lane >> 3, lr8 = lane & 7;
    const uint32_t laneA = ((uint32_t)((lm & 1)*8 + lr8))*GSTR_B + (uint32_t)(lm >> 1)*16;
    const uint32_t laneB = ((uint32_t)((lm >> 1)*8 + lr8))*GSTR_B + (uint32_t)(lm & 1)*16;

    if (tid < 128) bs[tid] = bias[n0 + tid];

    float c[2][8][4];
    #pragma unroll
    for (int i = 0; i < 2; i++)
        #pragma unroll
        for (int j = 0; j < 8; j++)
            #pragma unroll
            for (int k = 0; k < 4; k++) c[i][j][k] = 0.0f;

    const int lrow = tid >> 3;
    const int lcol = (tid & 7) << 2;
    const float* Ap = A + (size_t)(m0 + lrow) * HID + lcol;
    const float* Wp = W + (size_t)(n0 + lrow) * HID + lcol;

    float4 av[4], uv[4];
    #pragma unroll
    for (int i = 0; i < 4; i++) {
        av[i] = *(const float4*)(Ap + (size_t)i*32*HID);
        uv[i] = *(const float4*)(Wp + (size_t)i*32*HID);
    }
    #pragma unroll
    for (int i = 0; i < 4; i++) {
        float4 v = av[i];
        v.x = tf32r(v.x); v.y = tf32r(v.y); v.z = tf32r(v.z); v.w = tf32r(v.w);
        *(float4*)&sm[(lrow + i*32)*GPAD + lcol] = v;
        float4 u = uv[i];
        u.x = tf32r(u.x); u.y = tf32r(u.y); u.z = tf32r(u.z); u.w = tf32r(u.w);
        *(float4*)&sm[GBUF_F + (lrow + i*32)*GPAD + lcol] = u;
    }
    __syncthreads();

    #pragma unroll 1
    for (int ch = 0; ch < 16; ch++) {
        const int cur = ch & 1;
        if (ch < 15) {
            #pragma unroll
            for (int i = 0; i < 4; i++) {
                av[i] = *(const float4*)(Ap + (size_t)i*32*HID + (ch+1)*32);
                uv[i] = *(const float4*)(Wp + (size_t)i*32*HID + (ch+1)*32);
            }
        }
        const uint32_t abase = sb + cur*(2*GBUF_F*4) + (uint32_t)(warpM*32)*GSTR_B + laneA;
        const uint32_t bbase = sb + cur*(2*GBUF_F*4) + GBUF_F*4 + (uint32_t)(warpN*64)*GSTR_B + laneB;
        #pragma unroll
        for (int ks = 0; ks < 4; ks++) {
            uint32_t af[2][4];
            ldsm4(af[0], abase + ks*32);
            ldsm4(af[1], abase + 16*GSTR_B + ks*32);
            #pragma unroll
            for (int p = 0; p < 4; p++) {
                uint32_t bf[4];
                ldsm4(bf, bbase + (uint32_t)(p*16)*GSTR_B + ks*32);
                mma8(c[0][2*p],   af[0], bf);
                mma8(c[0][2*p+1], af[0], bf+2);
                mma8(c[1][2*p],   af[1], bf);
                mma8(c[1][2*p+1], af[1], bf+2);
            }
        }
        if (ch < 15) {
            float* dst = sm + (cur^1)*(2*GBUF_F);
            #pragma unroll
            for (int i = 0; i < 4; i++) {
                float4 v = av[i];
                v.x = tf32r(v.x); v.y = tf32r(v.y); v.z = tf32r(v.z); v.w = tf32r(v.w);
                *(float4*)&dst[(lrow + i*32)*GPAD + lcol] = v;
                float4 u = uv[i];
                u.x = tf32r(u.x); u.y = tf32r(u.y); u.z = tf32r(u.z); u.w = tf32r(u.w);
                *(float4*)&dst[GBUF_F + (lrow + i*32)*GPAD + lcol] = u;
            }
        }
        __syncthreads();
    }

    // epilogue
    #pragma unroll
    for (int mt = 0; mt < 2; mt++) {
        const int row = m0 + warpM*32 + mt*16 + g;
        #pragma unroll
        for (int nt = 0; nt < 8; nt++) {
            const int lc2 = warpN*64 + nt*8 + 2*t4;
            const float b0 = bs[lc2], b1 = bs[lc2+1];
            float2 v0 = make_float2(c[mt][nt][0] + b0, c[mt][nt][1] + b1);
            float2 v1 = make_float2(c[mt][nt][2] + b0, c[mt][nt][3] + b1);
            if (MODE == 2) { v0.x *= QSCALE; v0.y *= QSCALE; v1.x *= QSCALE; v1.y *= QSCALE; }
            if (MODE == 1 || MODE == 2) {
                v0.x = tf32r(v0.x); v0.y = tf32r(v0.y);
                v1.x = tf32r(v1.x); v1.y = tf32r(v1.y);
            }
            if (MODE == 0) {
                float* out = (float*)outv;
                *(float2*)&out[(size_t)row * HID + n0 + lc2] = v0;
                *(float2*)&out[(size_t)(row+8) * HID + n0 + lc2] = v1;
            } else if (MODE == 3) {
                __half* out = (__half*)outv;
                const int bi = row >> 11, s = row & 2047;
                const int cg = n0 + lc2;
                const int h = cg >> 6, d = cg & 63;
                __half* p = out + (((size_t)(bi*HH + h) * SS) + s) * DD + d;
                *(__half2*)p = __halves2half2(__float2half_rn(v0.x), __float2half_rn(v0.y));
                *(__half2*)(p + 8*DD) = __halves2half2(__float2half_rn(v1.x), __float2half_rn(v1.y));
            } else {
                float* out = (float*)outv;
                const int bi = row >> 11, s = row & 2047;
                const int cg = n0 + lc2;
                const int h = cg >> 6, d = cg & 63;
                float* p = out + (((size_t)(bi*HH + h) * SS) + s) * DD + d;
                *(float2*)p = v0;
                *(float2*)(p + 8*DD) = v1;
            }
        }
    }
}

// fused QKV projection
__global__ __launch_bounds__(256, 2)
void gemm_qkv(const float* __restrict__ x,
              const float* __restrict__ Wq, const float* __restrict__ bq,
              const float* __restrict__ Wk, const float* __restrict__ bk,
              const float* __restrict__ Wv, const float* __restrict__ bv,
              float* __restrict__ Qp, float* __restrict__ Kp, __half* __restrict__ Vp)
{
    extern __shared__ float sm[];
    const int m0 = blockIdx.x << 7, n0 = blockIdx.y << 7;
    if (blockIdx.z == 0)      gemm_core<2>(x, Wq, bq, Qp, sm, m0, n0);
    else if (blockIdx.z == 1) gemm_core<1>(x, Wk, bk, Kp, sm, m0, n0);
    else                      gemm_core<3>(x, Wv, bv, Vp, sm, m0, n0);
}

__global__ __launch_bounds__(256, 2)
void gemm_out(const float* __restrict__ A, const float* __restrict__ W,
              const float* __restrict__ bias, float* __restrict__ out)
{
    extern __shared__ float sm[];
    gemm_core<0>(A, W, bias, out, sm, blockIdx.x << 7, blockIdx.y << 7);
}

// ---------------------------------------------------------------------------
// Flash attention: S = QK^T in tf32 (m16n8k8), PV in fp16 (m16n8k16) with
// the FA2 accumulator->A-fragment reuse (cvt.f16x2 pack, zero shuffles).
// 8 warps x 16 query rows; 64-key tiles, cp.async double buffer.
// K smem [key][d] f32 stride 68 (272B); V smem [key][d] fp16 stride 72 (144B).
// ---------------------------------------------------------------------------
#define KSTR_B 272                 // 68 floats
#define KBUF_B (64*KSTR_B)         // 17408
#define VSTR_B 144                 // 72 halves
#define VBUF_B (64*VSTR_B)         // 9216
// bytes: K0=0, K1=17408, V0=34816, V1=44032; total 53248
__global__ __launch_bounds__(256, 2)
void attn_mma4(const float* __restrict__ Q, const float* __restrict__ K,
               const __half* __restrict__ V, float* __restrict__ ctx)
{
    extern __shared__ float sm[];
    const uint32_t sb = smem_u32(sm);
    const int tid = threadIdx.x;
    const int lane = tid & 31, warp = tid >> 5;
    const int g = lane >> 2, t4 = lane & 3;
    const int lm = lane >> 3, lr8 = lane & 7;
    // K B-frag lane offset: matrix m -> rows (m>>1)*8, colhalf m&1
    const uint32_t laneK = ((uint32_t)((lm >> 1)*8 + lr8))*KSTR_B + (uint32_t)(lm & 1)*16;
    // V trans-frag lane offset: matrix m -> krows (m&1)*8, dcol block (m>>1)*8
    const uint32_t laneV = ((uint32_t)((lm & 1)*8 + lr8))*VSTR_B + (uint32_t)(lm >> 1)*16;
    const int b = blockIdx.z, h = blockIdx.y;
    const int q0 = blockIdx.x << 7;

    const float* Qg = Q + ((size_t)(b*HH + h) * SS + q0) * DD;
    const float* Kg = K + (size_t)(b*HH + h) * SS * DD;
    const __half* Vg = V + (size_t)(b*HH + h) * SS * DD;

    // Q fragments (rows 16*warp+g, +8)
    uint32_t qf[8][4];
    {
        const uint32_t* q0p = (const uint32_t*)(Qg + (size_t)(warp*16 + g) * DD);
        const uint32_t* q1p = q0p + 8*DD;
        #pragma unroll
        for (int ks = 0; ks < 8; ks++) {
            qf[ks][0] = q0p[8*ks + t4];
            qf[ks][1] = q1p[8*ks + t4];
            qf[ks][2] = q0p[8*ks + t4 + 4];
            qf[ks][3] = q1p[8*ks + t4 + 4];
        }
    }

    // prologue: tile 0 -> buffer 0
    {
        #pragma unroll
        for (int i = 0; i < 4; i++) {       // K: 1024 16B chunks
            const int cc = tid + i*256;
            const int row = cc >> 4, col = cc & 15;
            cpasync16(sb + row*KSTR_B + col*16, Kg + (size_t)row*DD + col*4);
        }
        #pragma unroll
        for (int i = 0; i < 2; i++) {       // V: 512 16B chunks (fp16)
            const int cc = tid + i*256;
            const int row = cc >> 3, col = cc & 7;
            cpasync16(sb + 34816 + row*VSTR_B + col*16, Vg + (size_t)row*DD + col*8);
        }
        CP_COMMIT();
        CP_WAIT0();
    }
    __syncthreads();

    float o[8][4];
    #pragma unroll
    for (int j = 0; j < 8; j++)
        #pragma unroll
        for (int k = 0; k < 4; k++) o[j][k] = 0.0f;
    float m0r = -1.0e30f, m1r = -1.0e30f, l0r = 0.0f, l1r = 0.0f;

    #pragma unroll 1
    for (int t = 0; t < SS/64; t++) {
        const int cur = t & 1;
        const uint32_t kbase = sb + cur*KBUF_B + laneK;
        const uint32_t vbase = sb + 34816 + cur*VBUF_B + laneV;

        if (t < SS/64 - 1) {
            const uint32_t kd = sb + (cur^1)*KBUF_B;
            const uint32_t vd = sb + 34816 + (cur^1)*VBUF_B;
            const float* kn = Kg + (size_t)(t+1)*64*DD;
            const __half* vn = Vg + (size_t)(t+1)*64*DD;
            #pragma unroll
            for (int i = 0; i < 4; i++) {
                const int cc = tid + i*256;
                const int row = cc >> 4, col = cc & 15;
                cpasync16(kd + row*KSTR_B + col*16, kn + (size_t)row*DD + col*4);
            }
            #pragma unroll
            for (int i = 0; i < 2; i++) {
                const int cc = tid + i*256;
                const int row = cc >> 3, col = cc & 7;
                cpasync16(vd + row*VSTR_B + col*16, vn + (size_t)row*DD + col*8);
            }
            CP_COMMIT();
        }

        // S = Q K^T  (tf32)
        float sc[8][4];
        #pragma unroll
        for (int j = 0; j < 8; j++)
            #pragma unroll
            for (int k = 0; k < 4; k++) sc[j][k] = 0.0f;
        #pragma unroll
        for (int ks = 0; ks < 8; ks++) {
            #pragma unroll
            for (int p = 0; p < 4; p++) {
                uint32_t bf[4];
                ldsm4(bf, kbase + (uint32_t)(p*16)*KSTR_B + ks*32);
                mma8(sc[2*p],   qf[ks], bf);
                mma8(sc[2*p+1], qf[ks], bf+2);
            }
        }

        // online softmax (base-2), rows g and g+8
        float mx0 = -1.0e30f, mx1 = -1.0e30f;
        #pragma unroll
        for (int nt = 0; nt < 8; nt++) {
            mx0 = fmaxf(mx0, fmaxf(sc[nt][0], sc[nt][1]));
            mx1 = fmaxf(mx1, fmaxf(sc[nt][2], sc[nt][3]));
        }
        mx0 = fmaxf(mx0, __shfl_xor_sync(0xffffffffu, mx0, 1));
        mx0 = fmaxf(mx0, __shfl_xor_sync(0xffffffffu, mx0, 2));
        mx1 = fmaxf(mx1, __shfl_xor_sync(0xffffffffu, mx1, 1));
        mx1 = fmaxf(mx1, __shfl_xor_sync(0xffffffffu, mx1, 2));
        const float mn0 = fmaxf(m0r, mx0), mn1 = fmaxf(m1r, mx1);
        const float corr0 = ex2(m0r - mn0), corr1 = ex2(m1r - mn1);
        m0r = mn0; m1r = mn1;
        float sum0 = 0.0f, sum1 = 0.0f;
        #pragma unroll
        for (int nt = 0; nt < 8; nt++) {
            sc[nt][0] = ex2(sc[nt][0] - mn0);
            sc[nt][1] = ex2(sc[nt][1] - mn0);
            sc[nt][2] = ex2(sc[nt][2] - mn1);
            sc[nt][3] = ex2(sc[nt][3] - mn1);
            sum0 += sc[nt][0] + sc[nt][1];
            sum1 += sc[nt][2] + sc[nt][3];
        }
        sum0 += __shfl_xor_sync(0xffffffffu, sum0, 1);
        sum0 += __shfl_xor_sync(0xffffffffu, sum0, 2);
        sum1 += __shfl_xor_sync(0xffffffffu, sum1, 1);
        sum1 += __shfl_xor_sync(0xffffffffu, sum1, 2);
        l0r = l0r * corr0 + sum0;
        l1r = l1r * corr1 + sum1;

        #pragma unroll
        for (int nt = 0; nt < 8; nt++) {
            o[nt][0] *= corr0; o[nt][1] *= corr0;
            o[nt][2] *= corr1; o[nt][3] *= corr1;
        }

        // PV: O += P V  (fp16 m16n8k16; A-frags packed from S accumulators)
        #pragma unroll
        for (int j = 0; j < 4; j++) {          // 16-key blocks
            uint32_t af[4];
            af[0] = pkhf(sc[2*j][0],   sc[2*j][1]);
            af[1] = pkhf(sc[2*j][2],   sc[2*j][3]);
            af[2] = pkhf(sc[2*j+1][0], sc[2*j+1][1]);
            af[3] = pkhf(sc[2*j+1][2], sc[2*j+1][3]);
            #pragma unroll
            for (int p = 0; p < 4; p++) {      // 16-d blocks
                uint32_t bf[4];
                ldsm4t(bf, vbase + (uint32_t)(j*16)*VSTR_B + p*32);
                mma16(o[2*p],   af, bf);
                mma16(o[2*p+1], af, bf+2);
            }
        }

        CP_WAIT0();
        __syncthreads();
    }

    // epilogue
    const float inv0 = 1.0f / l0r, inv1 = 1.0f / l1r;
    const int row = q0 + warp*16 + g;
    #pragma unroll
    for (int nt = 0; nt < 8; nt++) {
        const int d = 8*nt + 2*t4;
        float* p = ctx + ((size_t)b * SS + row) * HID + h*DD + d;
        *(float2*)p = make_float2(o[nt][0]*inv0, o[nt][1]*inv0);
        *(float2*)(p + 8*HID) = make_float2(o[nt][2]*inv1, o[nt][3]*inv1);
    }
}

// ---------------------------------------------------------------------------
extern "C" void kernel_launch(void* const* d_in, const int* in_sizes, int n_in,
                              void* d_out, int out_size)
{
    (void)in_sizes; (void)n_in; (void)out_size;
    const float* x  = (const float*)d_in[0];
    const float* Wq = (const float*)d_in[1];
    const float* bq = (const float*)d_in[2];
    const float* Wk = (const float*)d_in[3];
    const float* bk = (const float*)d_in[4];
    const float* Wv = (const float*)d_in[5];
    const float* bv = (const float*)d_in[6];
    const float* Wo = (const float*)d_in[7];
    const float* bo = (const float*)d_in[8];
    float* out = (float*)d_out;

    float *Qp, *Kp, *Cp;
    __half* Vp;
    cudaGetSymbolAddress((void**)&Qp, g_Q);
    cudaGetSymbolAddress((void**)&Kp, g_K);
    cudaGetSymbolAddress((void**)&Vp, g_V);
    cudaGetSymbolAddress((void**)&Cp, g_C);

    const int gemm_smem = (4*GBUF_F + 128) * 4;   // 74240
    const int attn_smem = 53248;
    cudaFuncSetAttribute(gemm_qkv, cudaFuncAttributeMaxDynamicSharedMemorySize, gemm_smem);
    cudaFuncSetAttribute(gemm_out, cudaFuncAttributeMaxDynamicSharedMemorySize, gemm_smem);
    cudaFuncSetAttribute(attn_mma4, cudaFuncAttributeMaxDynamicSharedMemorySize, attn_smem);

    gemm_qkv<<<dim3(MT/128, HID/128, 3), 256, gemm_smem>>>(
        x, Wq, bq, Wk, bk, Wv, bv, Qp, Kp, Vp);

    attn_mma4<<<dim3(SS/128, HH, BB), 256, attn_smem>>>(Qp, Kp, Vp, Cp);

    gemm_out<<<dim3(MT/128, HID/128), 256, gemm_smem>>>(Cp, Wo, bo, out);
}

// round 9
// speedup vs baseline: 9.5044x; 1.3952x over previous
#include <cuda_runtime.h>
#include <cuda_fp16.h>
#include <cstdint>

// ---------------- problem constants ----------------
#define BB 4
#define SS 2048
#define HH 8
#define DD 64
#define HID 512
#define MT (BB*SS)   // 8192

// scratch
__device__ __half g_Q[MT*HID];     // [b,h,s,d]  pre-scaled by 0.125*log2e, fp16
__device__ __half g_K[MT*HID];     // [b,h,s,d]  fp16
__device__ __half g_V[MT*HID];     // [b,h,s,d]  fp16
__device__ float  g_C[MT*HID];     // ctx [b,s,hid] fp32

#define QSCALE 0.18033688011112042f   // 0.125 * log2(e)

__device__ __forceinline__ float ex2(float x){
    float r; asm("ex2.approx.ftz.f32 %0, %1;" : "=f"(r) : "f"(x)); return r;
}
// pack {lo, hi} floats into f16x2 (round-to-nearest)
__device__ __forceinline__ uint32_t pkhf(float lo, float hi){
    uint32_t d; asm("cvt.rn.f16x2.f32 %0, %1, %2;" : "=r"(d) : "f"(hi), "f"(lo)); return d;
}
__device__ __forceinline__ uint32_t smem_u32(const void* p){
    uint32_t a;
    asm("{ .reg .u64 t; cvta.to.shared.u64 t, %1; cvt.u32.u64 %0, t; }" : "=r"(a) : "l"(p));
    return a;
}
__device__ __forceinline__ void cpasync16(uint32_t dst, const void* src){
    asm volatile("cp.async.cg.shared.global [%0], [%1], 16;" :: "r"(dst), "l"(src) : "memory");
}
#define CP_COMMIT() asm volatile("cp.async.commit_group;" ::: "memory")
#define CP_WAIT0()  asm volatile("cp.async.wait_group 0;" ::: "memory")

// mma.sync m16n8k16 f16 (fp32 accumulate)
__device__ __forceinline__ void mma16(float* c, const uint32_t* a, const uint32_t* b){
    asm volatile("mma.sync.aligned.m16n8k16.row.col.f32.f16.f16.f32 "
        "{%0,%1,%2,%3}, {%4,%5,%6,%7}, {%8,%9}, {%0,%1,%2,%3};"
        : "+f"(c[0]), "+f"(c[1]), "+f"(c[2]), "+f"(c[3])
        : "r"(a[0]), "r"(a[1]), "r"(a[2]), "r"(a[3]), "r"(b[0]), "r"(b[1]));
}
// ldmatrix x4 (b16)
__device__ __forceinline__ void ldsm4(uint32_t* r, uint32_t addr){
    asm volatile("ldmatrix.sync.aligned.m8n8.x4.shared.b16 {%0,%1,%2,%3}, [%4];"
        : "=r"(r[0]), "=r"(r[1]), "=r"(r[2]), "=r"(r[3]) : "r"(addr));
}
// ldmatrix x4 transposed (b16)
__device__ __forceinline__ void ldsm4t(uint32_t* r, uint32_t addr){
    asm volatile("ldmatrix.sync.aligned.m8n8.x4.trans.shared.b16 {%0,%1,%2,%3}, [%4];"
        : "=r"(r[0]), "=r"(r[1]), "=r"(r[2]), "=r"(r[3]) : "r"(addr));
}

// ---------------------------------------------------------------------------
// GEMM core (fp16 operands, fp32 accum): out = A[M,512] @ W[Nblk,512]^T + b.
// CTA 128x128, BK=32, 8 warps = 4(M) x 2(N).  Double-buffered fp16 smem
// (gmem fp32 -> cvt.rn.f16x2 at STS), ldmatrix + m16n8k16.
// Tile stride 40 halves = 80 B (5r mod 8 permutation -> LDSM conflict-free).
// MODE 0: fp32 [m][512]   MODE 1: K fp16 [b,h,s,d]   MODE 2: Q scaled fp16
// MODE 3: V fp16 [b,h,s,d]
// ---------------------------------------------------------------------------
#define GPADH 40
#define GSTR_B 80
#define GBUF_H (128*GPADH)      // halves per matrix per stage (5120)
#define GSTAGE_B (2*GBUF_H*2)   // bytes per stage (A+W) = 20480

template<int MODE>
__device__ __forceinline__ void gemm_core(
    const float* __restrict__ A, const float* __restrict__ W,
    const float* __restrict__ bias, void* __restrict__ outv,
    char* smraw, int m0, int n0)
{
    __half* sh = (__half*)smraw;
    float* bs = (float*)(smraw + 2*GSTAGE_B);
    const uint32_t sb = smem_u32(smraw);

    const int tid = threadIdx.x;
    const int lane = tid & 31, warp = tid >> 5;
    const int g = lane >> 2, t4 = lane & 3;
    const int warpM = warp >> 1, warpN = warp & 1;
    const int lm = lane >> 3, lr8 = lane & 7;
    const uint32_t laneA = ((uint32_t)((lm & 1)*8 + lr8))*GSTR_B + (uint32_t)(lm >> 1)*16;
    const uint32_t laneB = ((uint32_t)((lm >> 1)*8 + lr8))*GSTR_B + (uint32_t)(lm & 1)*16;

    if (tid < 128) bs[tid] = bias[n0 + tid];

    float c[2][8][4];
    #pragma unroll
    for (int i = 0; i < 2; i++)
        #pragma unroll
        for (int j = 0; j < 8; j++)
            #pragma unroll
            for (int k = 0; k < 4; k++) c[i][j][k] = 0.0f;

    const int lrow = tid >> 3;          // 0..31
    const int lcol = (tid & 7) << 2;    // 0..28
    const float* Ap = A + (size_t)(m0 + lrow) * HID + lcol;
    const float* Wp = W + (size_t)(n0 + lrow) * HID + lcol;

    float4 av[4], uv[4];
    #pragma unroll
    for (int i = 0; i < 4; i++) {
        av[i] = *(const float4*)(Ap + (size_t)i*32*HID);
        uv[i] = *(const float4*)(Wp + (size_t)i*32*HID);
    }
    #pragma unroll
    for (int i = 0; i < 4; i++) {
        uint2 pa = make_uint2(pkhf(av[i].x, av[i].y), pkhf(av[i].z, av[i].w));
        *(uint2*)&sh[(lrow + i*32)*GPADH + lcol] = pa;
        uint2 pw = make_uint2(pkhf(uv[i].x, uv[i].y), pkhf(uv[i].z, uv[i].w));
        *(uint2*)&sh[GBUF_H + (lrow + i*32)*GPADH + lcol] = pw;
    }
    __syncthreads();

    #pragma unroll 1
    for (int ch = 0; ch < 16; ch++) {
        const int cur = ch & 1;
        if (ch < 15) {
            #pragma unroll
            for (int i = 0; i < 4; i++) {
                av[i] = *(const float4*)(Ap + (size_t)i*32*HID + (ch+1)*32);
                uv[i] = *(const float4*)(Wp + (size_t)i*32*HID + (ch+1)*32);
            }
        }
        const uint32_t abase = sb + cur*GSTAGE_B + (uint32_t)(warpM*32)*GSTR_B + laneA;
        const uint32_t bbase = sb + cur*GSTAGE_B + GBUF_H*2 + (uint32_t)(warpN*64)*GSTR_B + laneB;
        #pragma unroll
        for (int ks = 0; ks < 2; ks++) {        // 2 k-steps of 16
            uint32_t af[2][4];
            ldsm4(af[0], abase + ks*32);
            ldsm4(af[1], abase + 16*GSTR_B + ks*32);
            #pragma unroll
            for (int p = 0; p < 4; p++) {       // 16-n blocks
                uint32_t bf[4];
                ldsm4(bf, bbase + (uint32_t)(p*16)*GSTR_B + ks*32);
                mma16(c[0][2*p],   af[0], bf);
                mma16(c[0][2*p+1], af[0], bf+2);
                mma16(c[1][2*p],   af[1], bf);
                mma16(c[1][2*p+1], af[1], bf+2);
            }
        }
        if (ch < 15) {
            __half* dst = sh + (cur^1)*(2*GBUF_H);
            #pragma unroll
            for (int i = 0; i < 4; i++) {
                uint2 pa = make_uint2(pkhf(av[i].x, av[i].y), pkhf(av[i].z, av[i].w));
                *(uint2*)&dst[(lrow + i*32)*GPADH + lcol] = pa;
                uint2 pw = make_uint2(pkhf(uv[i].x, uv[i].y), pkhf(uv[i].z, uv[i].w));
                *(uint2*)&dst[GBUF_H + (lrow + i*32)*GPADH + lcol] = pw;
            }
        }
        __syncthreads();
    }

    // epilogue
    #pragma unroll
    for (int mt = 0; mt < 2; mt++) {
        const int row = m0 + warpM*32 + mt*16 + g;
        #pragma unroll
        for (int nt = 0; nt < 8; nt++) {
            const int lc2 = warpN*64 + nt*8 + 2*t4;
            const float b0 = bs[lc2], b1 = bs[lc2+1];
            float2 v0 = make_float2(c[mt][nt][0] + b0, c[mt][nt][1] + b1);
            float2 v1 = make_float2(c[mt][nt][2] + b0, c[mt][nt][3] + b1);
            if (MODE == 2) { v0.x *= QSCALE; v0.y *= QSCALE; v1.x *= QSCALE; v1.y *= QSCALE; }
            if (MODE == 0) {
                float* out = (float*)outv;
                *(float2*)&out[(size_t)row * HID + lc2 + n0] = v0;
                *(float2*)&out[(size_t)(row+8) * HID + lc2 + n0] = v1;
            } else {
                __half* out = (__half*)outv;
                const int bi = row >> 11, s = row & 2047;
                const int cg = n0 + lc2;
                const int h = cg >> 6, d = cg & 63;
                __half* p = out + (((size_t)(bi*HH + h) * SS) + s) * DD + d;
                *(uint32_t*)p = pkhf(v0.x, v0.y);
                *(uint32_t*)(p + 8*DD) = pkhf(v1.x, v1.y);
            }
        }
    }
}

// fused QKV projection
__global__ __launch_bounds__(256, 2)
void gemm_qkv(const float* __restrict__ x,
              const float* __restrict__ Wq, const float* __restrict__ bq,
              const float* __restrict__ Wk, const float* __restrict__ bk,
              const float* __restrict__ Wv, const float* __restrict__ bv,
              __half* __restrict__ Qp, __half* __restrict__ Kp, __half* __restrict__ Vp)
{
    extern __shared__ char smraw[];
    const int m0 = blockIdx.x << 7, n0 = blockIdx.y << 7;
    if (blockIdx.z == 0)      gemm_core<2>(x, Wq, bq, Qp, smraw, m0, n0);
    else if (blockIdx.z == 1) gemm_core<1>(x, Wk, bk, Kp, smraw, m0, n0);
    else                      gemm_core<3>(x, Wv, bv, Vp, smraw, m0, n0);
}

__global__ __launch_bounds__(256, 2)
void gemm_out(const float* __restrict__ A, const float* __restrict__ W,
              const float* __restrict__ bias, float* __restrict__ out)
{
    extern __shared__ char smraw[];
    gemm_core<0>(A, W, bias, out, smraw, blockIdx.x << 7, blockIdx.y << 7);
}

// ---------------------------------------------------------------------------
// Flash attention, all-fp16 operands (fp32 accum/softmax).
// S = QK^T fp16 m16n8k16; PV fp16 m16n8k16 with accumulator->A reuse.
// 8 warps x 16 query rows; 64-key tiles, cp.async double buffer.
// K,V smem [key/d rows][64 halves] stride 72 halves = 144 B (9r mod 8
// permutation -> LDSM conflict-free).
// ---------------------------------------------------------------------------
#define ASTR_B 144                 // 72 halves
#define ABUF_B (64*ASTR_B)         // 9216
// bytes: K0=0, K1=9216, V0=18432, V1=27648; total 36864
__global__ __launch_bounds__(256, 2)
void attn_mma5(const __half* __restrict__ Q, const __half* __restrict__ K,
               const __half* __restrict__ V, float* __restrict__ ctx)
{
    extern __shared__ char smraw[];
    const uint32_t sb = smem_u32(smraw);
    const int tid = threadIdx.x;
    const int lane = tid & 31, warp = tid >> 5;
    const int g = lane >> 2, t4 = lane & 3;
    const int lm = lane >> 3, lr8 = lane & 7;
    // K B-frag (non-trans): matrix m -> rows (m>>1)*8, k-half m&1
    const uint32_t laneK = ((uint32_t)((lm >> 1)*8 + lr8))*ASTR_B + (uint32_t)(lm & 1)*16;
    // V B-frag (trans): matrix m -> k-rows (m&1)*8, d-block (m>>1)*8
    const uint32_t laneV = ((uint32_t)((lm & 1)*8 + lr8))*ASTR_B + (uint32_t)(lm >> 1)*16;
    const int b = blockIdx.z, h = blockIdx.y;
    const int q0 = blockIdx.x << 7;

    const __half* Qg = Q + ((size_t)(b*HH + h) * SS + q0) * DD;
    const __half* Kg = K + (size_t)(b*HH + h) * SS * DD;
    const __half* Vg = V + (size_t)(b*HH + h) * SS * DD;

    // Q fragments (rows 16*warp+g, +8): 4 k-steps of 16
    uint32_t qf[4][4];
    {
        const uint32_t* q0p = (const uint32_t*)(Qg + (size_t)(warp*16 + g) * DD);
        const uint32_t* q1p = q0p + 4*DD;   // +8 rows of 64 halves = 256 u32? no: 8*64/2 = 256... (see below)
        // 8 rows * DD halves = 8*64 = 512 halves = 256 u32
        const uint32_t* q1pp = q0p + 256;
        #pragma unroll
        for (int ks = 0; ks < 4; ks++) {
            qf[ks][0] = q0p[8*ks + t4];
            qf[ks][1] = q1pp[8*ks + t4];
            qf[ks][2] = q0p[8*ks + 4 + t4];
            qf[ks][3] = q1pp[8*ks + 4 + t4];
        }
        (void)q1p;
    }

    // prologue: tile 0 -> buffer 0  (K and V: 512 16B chunks each)
    {
        #pragma unroll
        for (int i = 0; i < 2; i++) {
            const int cc = tid + i*256;
            const int row = cc >> 3, col = cc & 7;
            cpasync16(sb + row*ASTR_B + col*16, Kg + (size_t)row*DD + col*8);
            cpasync16(sb + 18432 + row*ASTR_B + col*16, Vg + (size_t)row*DD + col*8);
        }
        CP_COMMIT();
        CP_WAIT0();
    }
    __syncthreads();

    float o[8][4];
    #pragma unroll
    for (int j = 0; j < 8; j++)
        #pragma unroll
        for (int k = 0; k < 4; k++) o[j][k] = 0.0f;
    float m0r = -1.0e30f, m1r = -1.0e30f, l0r = 0.0f, l1r = 0.0f;

    #pragma unroll 1
    for (int t = 0; t < SS/64; t++) {
        const int cur = t & 1;
        const uint32_t kbase = sb + cur*ABUF_B + laneK;
        const uint32_t vbase = sb + 18432 + cur*ABUF_B + laneV;

        if (t < SS/64 - 1) {
            const uint32_t kd = sb + (cur^1)*ABUF_B;
            const uint32_t vd = sb + 18432 + (cur^1)*ABUF_B;
            const __half* kn = Kg + (size_t)(t+1)*64*DD;
            const __half* vn = Vg + (size_t)(t+1)*64*DD;
            #pragma unroll
            for (int i = 0; i < 2; i++) {
                const int cc = tid + i*256;
                const int row = cc >> 3, col = cc & 7;
                cpasync16(kd + row*ASTR_B + col*16, kn + (size_t)row*DD + col*8);
                cpasync16(vd + row*ASTR_B + col*16, vn + (size_t)row*DD + col*8);
            }
            CP_COMMIT();
        }

        // S = Q K^T  (fp16, 4 k-steps x 4 key-blocks)
        float sc[8][4];
        #pragma unroll
        for (int j = 0; j < 8; j++)
            #pragma unroll
            for (int k = 0; k < 4; k++) sc[j][k] = 0.0f;
        #pragma unroll
        for (int ks = 0; ks < 4; ks++) {
            #pragma unroll
            for (int p = 0; p < 4; p++) {
                uint32_t bf[4];
                ldsm4(bf, kbase + (uint32_t)(p*16)*ASTR_B + ks*32);
                mma16(sc[2*p],   qf[ks], bf);
                mma16(sc[2*p+1], qf[ks], bf+2);
            }
        }

        // online softmax (base-2), rows g and g+8
        float mx0 = -1.0e30f, mx1 = -1.0e30f;
        #pragma unroll
        for (int nt = 0; nt < 8; nt++) {
            mx0 = fmaxf(mx0, fmaxf(sc[nt][0], sc[nt][1]));
            mx1 = fmaxf(mx1, fmaxf(sc[nt][2], sc[nt][3]));
        }
        mx0 = fmaxf(mx0, __shfl_xor_sync(0xffffffffu, mx0, 1));
        mx0 = fmaxf(mx0, __shfl_xor_sync(0xffffffffu, mx0, 2));
        mx1 = fmaxf(mx1, __shfl_xor_sync(0xffffffffu, mx1, 1));
        mx1 = fmaxf(mx1, __shfl_xor_sync(0xffffffffu, mx1, 2));
        const float mn0 = fmaxf(m0r, mx0), mn1 = fmaxf(m1r, mx1);
        const float corr0 = ex2(m0r - mn0), corr1 = ex2(m1r - mn1);
        m0r = mn0; m1r = mn1;
        float sum0 = 0.0f, sum1 = 0.0f;
        #pragma unroll
        for (int nt = 0; nt < 8; nt++) {
            sc[nt][0] = ex2(sc[nt][0] - mn0);
            sc[nt][1] = ex2(sc[nt][1] - mn0);
            sc[nt][2] = ex2(sc[nt][2] - mn1);
            sc[nt][3] = ex2(sc[nt][3] - mn1);
            sum0 += sc[nt][0] + sc[nt][1];
            sum1 += sc[nt][2] + sc[nt][3];
        }
        sum0 += __shfl_xor_sync(0xffffffffu, sum0, 1);
        sum0 += __shfl_xor_sync(0xffffffffu, sum0, 2);
        sum1 += __shfl_xor_sync(0xffffffffu, sum1, 1);
        sum1 += __shfl_xor_sync(0xffffffffu, sum1, 2);
        l0r = l0r * corr0 + sum0;
        l1r = l1r * corr1 + sum1;

        #pragma unroll
        for (int nt = 0; nt < 8; nt++) {
            o[nt][0] *= corr0; o[nt][1] *= corr0;
            o[nt][2] *= corr1; o[nt][3] *= corr1;
        }

        // PV: O += P V  (A-frags packed from S accumulators)
        #pragma unroll
        for (int j = 0; j < 4; j++) {          // 16-key blocks
            uint32_t af[4];
            af[0] = pkhf(sc[2*j][0],   sc[2*j][1]);
            af[1] = pkhf(sc[2*j][2],   sc[2*j][3]);
            af[2] = pkhf(sc[2*j+1][0], sc[2*j+1][1]);
            af[3] = pkhf(sc[2*j+1][2], sc[2*j+1][3]);
            #pragma unroll
            for (int p = 0; p < 4; p++) {      // 16-d blocks
                uint32_t bf[4];
                ldsm4t(bf, vbase + (uint32_t)(j*16)*ASTR_B + p*32);
                mma16(o[2*p],   af, bf);
                mma16(o[2*p+1], af, bf+2);
            }
        }

        CP_WAIT0();
        __syncthreads();
    }

    // epilogue
    const float inv0 = 1.0f / l0r, inv1 = 1.0f / l1r;
    const int row = q0 + warp*16 + g;
    #pragma unroll
    for (int nt = 0; nt < 8; nt++) {
        const int d = 8*nt + 2*t4;
        float* p = ctx + ((size_t)b * SS + row) * HID + h*DD + d;
        *(float2*)p = make_float2(o[nt][0]*inv0, o[nt][1]*inv0);
        *(float2*)(p + 8*HID) = make_float2(o[nt][2]*inv1, o[nt][3]*inv1);
    }
}

// ---------------------------------------------------------------------------
extern "C" void kernel_launch(void* const* d_in, const int* in_sizes, int n_in,
                              void* d_out, int out_size)
{
    (void)in_sizes; (void)n_in; (void)out_size;
    const float* x  = (const float*)d_in[0];
    const float* Wq = (const float*)d_in[1];
    const float* bq = (const float*)d_in[2];
    const float* Wk = (const float*)d_in[3];
    const float* bk = (const float*)d_in[4];
    const float* Wv = (const float*)d_in[5];
    const float* bv = (const float*)d_in[6];
    const float* Wo = (const float*)d_in[7];
    const float* bo = (const float*)d_in[8];
    float* out = (float*)d_out;

    __half *Qp, *Kp, *Vp;
    float *Cp;
    cudaGetSymbolAddress((void**)&Qp, g_Q);
    cudaGetSymbolAddress((void**)&Kp, g_K);
    cudaGetSymbolAddress((void**)&Vp, g_V);
    cudaGetSymbolAddress((void**)&Cp, g_C);

    const int gemm_smem = 2*GSTAGE_B + 512;   // 41472
    const int attn_smem = 36864;
    cudaFuncSetAttribute(gemm_qkv, cudaFuncAttributeMaxDynamicSharedMemorySize, gemm_smem);
    cudaFuncSetAttribute(gemm_out, cudaFuncAttributeMaxDynamicSharedMemorySize, gemm_smem);
    cudaFuncSetAttribute(attn_mma5, cudaFuncAttributeMaxDynamicSharedMemorySize, attn_smem);

    gemm_qkv<<<dim3(MT/128, HID/128, 3), 256, gemm_smem>>>(
        x, Wq, bq, Wk, bk, Wv, bv, Qp, Kp, Vp);

    attn_mma5<<<dim3(SS/128, HH, BB), 256, attn_smem>>>(Qp, Kp, Vp, Cp);

    gemm_out<<<dim3(MT/128, HID/128), 256, gemm_smem>>>(Cp, Wo, bo, out);
}

// round 10
// speedup vs baseline: 10.0089x; 1.0531x over previous
#include <cuda_runtime.h>
#include <cuda_fp16.h>
#include <cstdint>

// ---------------- problem constants ----------------
#define BB 4
#define SS 2048
#define HH 8
#define DD 64
#define HID 512
#define MT (BB*SS)   // 8192

// scratch (all fp16 intermediates)
__device__ __half g_X[MT*HID];        // x fp16
__device__ __half g_Wh[4*HID*HID];    // Wq,Wk,Wv,Wo fp16
__device__ __half g_Q[MT*HID];        // [b,h,s,d] pre-scaled by 0.125*log2e
__device__ __half g_K[MT*HID];        // [b,h,s,d]
__device__ __half g_V[MT*HID];        // [b,h,s,d]
__device__ __half g_C[MT*HID];        // ctx [b,s,hid] fp16

#define QSCALE 0.18033688011112042f   // 0.125 * log2(e)

__device__ __forceinline__ float ex2(float x){
    float r; asm("ex2.approx.ftz.f32 %0, %1;" : "=f"(r) : "f"(x)); return r;
}
__device__ __forceinline__ uint32_t pkhf(float lo, float hi){
    uint32_t d; asm("cvt.rn.f16x2.f32 %0, %1, %2;" : "=r"(d) : "f"(hi), "f"(lo)); return d;
}
__device__ __forceinline__ uint32_t smem_u32(const void* p){
    uint32_t a;
    asm("{ .reg .u64 t; cvta.to.shared.u64 t, %1; cvt.u32.u64 %0, t; }" : "=r"(a) : "l"(p));
    return a;
}
__device__ __forceinline__ void cpasync16(uint32_t dst, const void* src){
    asm volatile("cp.async.cg.shared.global [%0], [%1], 16;" :: "r"(dst), "l"(src) : "memory");
}
#define CP_COMMIT() asm volatile("cp.async.commit_group;" ::: "memory")
#define CP_WAIT0()  asm volatile("cp.async.wait_group 0;" ::: "memory")
#define CP_WAIT2()  asm volatile("cp.async.wait_group 2;" ::: "memory")

// mma.sync m16n8k16 f16 (fp32 accumulate)
__device__ __forceinline__ void mma16(float* c, const uint32_t* a, const uint32_t* b){
    asm volatile("mma.sync.aligned.m16n8k16.row.col.f32.f16.f16.f32 "
        "{%0,%1,%2,%3}, {%4,%5,%6,%7}, {%8,%9}, {%0,%1,%2,%3};"
        : "+f"(c[0]), "+f"(c[1]), "+f"(c[2]), "+f"(c[3])
        : "r"(a[0]), "r"(a[1]), "r"(a[2]), "r"(a[3]), "r"(b[0]), "r"(b[1]));
}
__device__ __forceinline__ void ldsm4(uint32_t* r, uint32_t addr){
    asm volatile("ldmatrix.sync.aligned.m8n8.x4.shared.b16 {%0,%1,%2,%3}, [%4];"
        : "=r"(r[0]), "=r"(r[1]), "=r"(r[2]), "=r"(r[3]) : "r"(addr));
}
__device__ __forceinline__ void ldsm4t(uint32_t* r, uint32_t addr){
    asm volatile("ldmatrix.sync.aligned.m8n8.x4.trans.shared.b16 {%0,%1,%2,%3}, [%4];"
        : "=r"(r[0]), "=r"(r[1]), "=r"(r[2]), "=r"(r[3]) : "r"(addr));
}

// ---------------------------------------------------------------------------
// fp32 -> fp16 pre-conversion: x (1048576 float4) + 4 weights (65536 each).
// Rounding points identical to the previous in-GEMM cvt -> rel_err unchanged.
// ---------------------------------------------------------------------------
__global__ __launch_bounds__(256)
void cvt_inputs(const float* __restrict__ x,
                const float* __restrict__ Wq, const float* __restrict__ Wk,
                const float* __restrict__ Wv, const float* __restrict__ Wo,
                __half* __restrict__ Xh, __half* __restrict__ Wh)
{
    const int flat = blockIdx.x * 256 + threadIdx.x;   // float4 index
    const float* src; uint2* dst; int off;
    if (flat < 1048576) { src = x; dst = (uint2*)Xh; off = flat; }
    else {
        const int w = (flat - 1048576) >> 16;
        off = (flat - 1048576) & 65535;
        src = (w == 0) ? Wq : (w == 1) ? Wk : (w == 2) ? Wv : Wo;
        dst = (uint2*)(Wh + (size_t)w * HID * HID);
    }
    float4 v = ((const float4*)src)[off];
    dst[off] = make_uint2(pkhf(v.x, v.y), pkhf(v.z, v.w));
}

// ---------------------------------------------------------------------------
// GEMM core (fp16 in gmem): out = A[M,512] @ W[Nblk,512]^T + bias.
// CTA 128x128, BK=32, 8 warps = 4(M) x 2(N).  4-stage cp.async pipeline.
// Tile stride 40 halves = 80 B (5r mod 8 permutation -> LDSM conflict-free).
// MODE 0: fp32 [m][512]   MODE 1: K fp16 [b,h,s,d]   MODE 2: Q scaled fp16
// MODE 3: V fp16 [b,h,s,d]
// ---------------------------------------------------------------------------
#define GPADH 40
#define GSTR_B 80
#define GBUF_H (128*GPADH)      // halves per matrix per stage (5120)
#define GSTAGE_B (2*GBUF_H*2)   // bytes per stage (A+W) = 20480
#define NSTG 4

template<int MODE>
__device__ __forceinline__ void gemm_core(
    const __half* __restrict__ A, const __half* __restrict__ W,
    const float* __restrict__ bias, void* __restrict__ outv,
    char* smraw, int m0, int n0)
{
    float* bs = (float*)(smraw + NSTG*GSTAGE_B);
    const uint32_t sb = smem_u32(smraw);

    const int tid = threadIdx.x;
    const int lane = tid & 31, warp = tid >> 5;
    const int g = lane >> 2, t4 = lane & 3;
    const int warpM = warp >> 1, warpN = warp & 1;
    const int lm = lane >> 3, lr8 = lane & 7;
    const uint32_t laneA = ((uint32_t)((lm & 1)*8 + lr8))*GSTR_B + (uint32_t)(lm >> 1)*16;
    const uint32_t laneB = ((uint32_t)((lm >> 1)*8 + lr8))*GSTR_B + (uint32_t)(lm & 1)*16;

    if (tid < 128) bs[tid] = bias[n0 + tid];

    // per-thread cp.async assignment: 2 chunks A + 2 chunks W per stage
    const int r0 = tid >> 2, c0 = tid & 3;            // A chunk 0: rows 0..63
    const int r1 = r0 + 64;                           // A chunk 1
    const __half* Asrc0 = A + (size_t)(m0 + r0) * HID + c0*8;
    const __half* Asrc1 = A + (size_t)(m0 + r1) * HID + c0*8;
    const __half* Wsrc0 = W + (size_t)(n0 + r0) * HID + c0*8;
    const __half* Wsrc1 = W + (size_t)(n0 + r1) * HID + c0*8;
    const uint32_t dA0 = (uint32_t)r0*GSTR_B + (uint32_t)c0*16;
    const uint32_t dA1 = (uint32_t)r1*GSTR_B + (uint32_t)c0*16;

    float c[2][8][4];
    #pragma unroll
    for (int i = 0; i < 2; i++)
        #pragma unroll
        for (int j = 0; j < 8; j++)
            #pragma unroll
            for (int k = 0; k < 4; k++) c[i][j][k] = 0.0f;

    // prologue: fill stages 0..2 with chunks 0..2
    #pragma unroll
    for (int s = 0; s < NSTG-1; s++) {
        const uint32_t st = sb + s*GSTAGE_B;
        cpasync16(st + dA0, Asrc0 + s*32);
        cpasync16(st + dA1, Asrc1 + s*32);
        cpasync16(st + GBUF_H*2 + dA0, Wsrc0 + s*32);
        cpasync16(st + GBUF_H*2 + dA1, Wsrc1 + s*32);
        CP_COMMIT();
    }

    #pragma unroll 1
    for (int ch = 0; ch < 16; ch++) {
        const int cur = ch & (NSTG-1);
        CP_WAIT2();
        __syncthreads();

        const uint32_t abase = sb + cur*GSTAGE_B + (uint32_t)(warpM*32)*GSTR_B + laneA;
        const uint32_t bbase = sb + cur*GSTAGE_B + GBUF_H*2 + (uint32_t)(warpN*64)*GSTR_B + laneB;
        #pragma unroll
        for (int ks = 0; ks < 2; ks++) {
            uint32_t af[2][4];
            ldsm4(af[0], abase + ks*32);
            ldsm4(af[1], abase + 16*GSTR_B + ks*32);
            #pragma unroll
            for (int p = 0; p < 4; p++) {
                uint32_t bf[4];
                ldsm4(bf, bbase + (uint32_t)(p*16)*GSTR_B + ks*32);
                mma16(c[0][2*p],   af[0], bf);
                mma16(c[0][2*p+1], af[0], bf+2);
                mma16(c[1][2*p],   af[1], bf);
                mma16(c[1][2*p+1], af[1], bf+2);
            }
        }
        __syncthreads();   // all reads of the stage being overwritten next are done
        if (ch + NSTG - 1 < 16) {
            const int nch = ch + NSTG - 1;
            const uint32_t st = sb + (nch & (NSTG-1))*GSTAGE_B;
            cpasync16(st + dA0, Asrc0 + nch*32);
            cpasync16(st + dA1, Asrc1 + nch*32);
            cpasync16(st + GBUF_H*2 + dA0, Wsrc0 + nch*32);
            cpasync16(st + GBUF_H*2 + dA1, Wsrc1 + nch*32);
        }
        CP_COMMIT();       // empty groups at the tail keep wait_group arithmetic valid
    }

    // epilogue
    #pragma unroll
    for (int mt = 0; mt < 2; mt++) {
        const int row = m0 + warpM*32 + mt*16 + g;
        #pragma unroll
        for (int nt = 0; nt < 8; nt++) {
            const int lc2 = warpN*64 + nt*8 + 2*t4;
            const float b0 = bs[lc2], b1 = bs[lc2+1];
            float2 v0 = make_float2(c[mt][nt][0] + b0, c[mt][nt][1] + b1);
            float2 v1 = make_float2(c[mt][nt][2] + b0, c[mt][nt][3] + b1);
            if (MODE == 2) { v0.x *= QSCALE; v0.y *= QSCALE; v1.x *= QSCALE; v1.y *= QSCALE; }
            if (MODE == 0) {
                float* out = (float*)outv;
                *(float2*)&out[(size_t)row * HID + n0 + lc2] = v0;
                *(float2*)&out[(size_t)(row+8) * HID + n0 + lc2] = v1;
            } else {
                __half* out = (__half*)outv;
                const int bi = row >> 11, s = row & 2047;
                const int cg = n0 + lc2;
                const int h = cg >> 6, d = cg & 63;
                __half* p = out + (((size_t)(bi*HH + h) * SS) + s) * DD + d;
                *(uint32_t*)p = pkhf(v0.x, v0.y);
                *(uint32_t*)(p + 8*DD) = pkhf(v1.x, v1.y);
            }
        }
    }
}

// fused QKV projection
__global__ __launch_bounds__(256, 2)
void gemm_qkv(const __half* __restrict__ x, const __half* __restrict__ Wh,
              const float* __restrict__ bq, const float* __restrict__ bk,
              const float* __restrict__ bv,
              __half* __restrict__ Qp, __half* __restrict__ Kp, __half* __restrict__ Vp)
{
    extern __shared__ char smraw[];
    const int m0 = blockIdx.x << 7, n0 = blockIdx.y << 7;
    if (blockIdx.z == 0)      gemm_core<2>(x, Wh,               bq, Qp, smraw, m0, n0);
    else if (blockIdx.z == 1) gemm_core<1>(x, Wh +   HID*HID,   bk, Kp, smraw, m0, n0);
    else                      gemm_core<3>(x, Wh + 2*HID*HID,   bv, Vp, smraw, m0, n0);
}

__global__ __launch_bounds__(256, 2)
void gemm_out(const __half* __restrict__ A, const __half* __restrict__ W,
              const float* __restrict__ bias, float* __restrict__ out)
{
    extern __shared__ char smraw[];
    gemm_core<0>(A, W, bias, out, smraw, blockIdx.x << 7, blockIdx.y << 7);
}

// ---------------------------------------------------------------------------
// Flash attention, all-fp16 operands (fp32 accum/softmax).
// S = QK^T fp16 m16n8k16; PV fp16 m16n8k16 with accumulator->A reuse.
// 8 warps x 16 query rows; 64-key tiles, cp.async double buffer.
// ctx written as fp16 (same rounding point the output GEMM used before).
// ---------------------------------------------------------------------------
#define ASTR_B 144                 // 72 halves
#define ABUF_B (64*ASTR_B)         // 9216
// bytes: K0=0, K1=9216, V0=18432, V1=27648; total 36864
__global__ __launch_bounds__(256, 2)
void attn_mma5(const __half* __restrict__ Q, const __half* __restrict__ K,
               const __half* __restrict__ V, __half* __restrict__ ctx)
{
    extern __shared__ char smraw[];
    const uint32_t sb = smem_u32(smraw);
    const int tid = threadIdx.x;
    const int lane = tid & 31, warp = tid >> 5;
    const int g = lane >> 2, t4 = lane & 3;
    const int lm = lane >> 3, lr8 = lane & 7;
    const uint32_t laneK = ((uint32_t)((lm >> 1)*8 + lr8))*ASTR_B + (uint32_t)(lm & 1)*16;
    const uint32_t laneV = ((uint32_t)((lm & 1)*8 + lr8))*ASTR_B + (uint32_t)(lm >> 1)*16;
    const int b = blockIdx.z, h = blockIdx.y;
    const int q0 = blockIdx.x << 7;

    const __half* Qg = Q + ((size_t)(b*HH + h) * SS + q0) * DD;
    const __half* Kg = K + (size_t)(b*HH + h) * SS * DD;
    const __half* Vg = V + (size_t)(b*HH + h) * SS * DD;

    // Q fragments (rows 16*warp+g, +8): 4 k-steps of 16
    uint32_t qf[4][4];
    {
        const uint32_t* q0p = (const uint32_t*)(Qg + (size_t)(warp*16 + g) * DD);
        const uint32_t* q1p = q0p + 256;   // +8 rows * 64 halves = 256 u32
        #pragma unroll
        for (int ks = 0; ks < 4; ks++) {
            qf[ks][0] = q0p[8*ks + t4];
            qf[ks][1] = q1p[8*ks + t4];
            qf[ks][2] = q0p[8*ks + 4 + t4];
            qf[ks][3] = q1p[8*ks + 4 + t4];
        }
    }

    // prologue
    {
        #pragma unroll
        for (int i = 0; i < 2; i++) {
            const int cc = tid + i*256;
            const int row = cc >> 3, col = cc & 7;
            cpasync16(sb + row*ASTR_B + col*16, Kg + (size_t)row*DD + col*8);
            cpasync16(sb + 18432 + row*ASTR_B + col*16, Vg + (size_t)row*DD + col*8);
        }
        CP_COMMIT();
        CP_WAIT0();
    }
    __syncthreads();

    float o[8][4];
    #pragma unroll
    for (int j = 0; j < 8; j++)
        #pragma unroll
        for (int k = 0; k < 4; k++) o[j][k] = 0.0f;
    float m0r = -1.0e30f, m1r = -1.0e30f, l0r = 0.0f, l1r = 0.0f;

    #pragma unroll 1
    for (int t = 0; t < SS/64; t++) {
        const int cur = t & 1;
        const uint32_t kbase = sb + cur*ABUF_B + laneK;
        const uint32_t vbase = sb + 18432 + cur*ABUF_B + laneV;

        if (t < SS/64 - 1) {
            const uint32_t kd = sb + (cur^1)*ABUF_B;
            const uint32_t vd = sb + 18432 + (cur^1)*ABUF_B;
            const __half* kn = Kg + (size_t)(t+1)*64*DD;
            const __half* vn = Vg + (size_t)(t+1)*64*DD;
            #pragma unroll
            for (int i = 0; i < 2; i++) {
                const int cc = tid + i*256;
                const int row = cc >> 3, col = cc & 7;
                cpasync16(kd + row*ASTR_B + col*16, kn + (size_t)row*DD + col*8);
                cpasync16(vd + row*ASTR_B + col*16, vn + (size_t)row*DD + col*8);
            }
            CP_COMMIT();
        }

        // S = Q K^T
        float sc[8][4];
        #pragma unroll
        for (int j = 0; j < 8; j++)
            #pragma unroll
            for (int k = 0; k < 4; k++) sc[j][k] = 0.0f;
        #pragma unroll
        for (int ks = 0; ks < 4; ks++) {
            #pragma unroll
            for (int p = 0; p < 4; p++) {
                uint32_t bf[4];
                ldsm4(bf, kbase + (uint32_t)(p*16)*ASTR_B + ks*32);
                mma16(sc[2*p],   qf[ks], bf);
                mma16(sc[2*p+1], qf[ks], bf+2);
            }
        }

        // online softmax (base-2), rows g and g+8
        float mx0 = -1.0e30f, mx1 = -1.0e30f;
        #pragma unroll
        for (int nt = 0; nt < 8; nt++) {
            mx0 = fmaxf(mx0, fmaxf(sc[nt][0], sc[nt][1]));
            mx1 = fmaxf(mx1, fmaxf(sc[nt][2], sc[nt][3]));
        }
        mx0 = fmaxf(mx0, __shfl_xor_sync(0xffffffffu, mx0, 1));
        mx0 = fmaxf(mx0, __shfl_xor_sync(0xffffffffu, mx0, 2));
        mx1 = fmaxf(mx1, __shfl_xor_sync(0xffffffffu, mx1, 1));
        mx1 = fmaxf(mx1, __shfl_xor_sync(0xffffffffu, mx1, 2));
        const float mn0 = fmaxf(m0r, mx0), mn1 = fmaxf(m1r, mx1);
        const float corr0 = ex2(m0r - mn0), corr1 = ex2(m1r - mn1);
        m0r = mn0; m1r = mn1;
        float sum0 = 0.0f, sum1 = 0.0f;
        #pragma unroll
        for (int nt = 0; nt < 8; nt++) {
            sc[nt][0] = ex2(sc[nt][0] - mn0);
            sc[nt][1] = ex2(sc[nt][1] - mn0);
            sc[nt][2] = ex2(sc[nt][2] - mn1);
            sc[nt][3] = ex2(sc[nt][3] - mn1);
            sum0 += sc[nt][0] + sc[nt][1];
            sum1 += sc[nt][2] + sc[nt][3];
        }
        sum0 += __shfl_xor_sync(0xffffffffu, sum0, 1);
        sum0 += __shfl_xor_sync(0xffffffffu, sum0, 2);
        sum1 += __shfl_xor_sync(0xffffffffu, sum1, 1);
        sum1 += __shfl_xor_sync(0xffffffffu, sum1, 2);
        l0r = l0r * corr0 + sum0;
        l1r = l1r * corr1 + sum1;

        #pragma unroll
        for (int nt = 0; nt < 8; nt++) {
            o[nt][0] *= corr0; o[nt][1] *= corr0;
            o[nt][2] *= corr1; o[nt][3] *= corr1;
        }

        // PV: O += P V
        #pragma unroll
        for (int j = 0; j < 4; j++) {
            uint32_t af[4];
            af[0] = pkhf(sc[2*j][0],   sc[2*j][1]);
            af[1] = pkhf(sc[2*j][2],   sc[2*j][3]);
            af[2] = pkhf(sc[2*j+1][0], sc[2*j+1][1]);
            af[3] = pkhf(sc[2*j+1][2], sc[2*j+1][3]);
            #pragma unroll
            for (int p = 0; p < 4; p++) {
                uint32_t bf[4];
                ldsm4t(bf, vbase + (uint32_t)(j*16)*ASTR_B + p*32);
                mma16(o[2*p],   af, bf);
                mma16(o[2*p+1], af, bf+2);
            }
        }

        CP_WAIT0();
        __syncthreads();
    }

    // epilogue: ctx fp16 [b, s, hid]
    const float inv0 = 1.0f / l0r, inv1 = 1.0f / l1r;
    const int row = q0 + warp*16 + g;
    #pragma unroll
    for (int nt = 0; nt < 8; nt++) {
        const int d = 8*nt + 2*t4;
        __half* p = ctx + ((size_t)b * SS + row) * HID + h*DD + d;
        *(uint32_t*)p = pkhf(o[nt][0]*inv0, o[nt][1]*inv0);
        *(uint32_t*)(p + 8*HID) = pkhf(o[nt][2]*inv1, o[nt][3]*inv1);
    }
}

// ---------------------------------------------------------------------------
extern "C" void kernel_launch(void* const* d_in, const int* in_sizes, int n_in,
                              void* d_out, int out_size)
{
    (void)in_sizes; (void)n_in; (void)out_size;
    const float* x  = (const float*)d_in[0];
    const float* Wq = (const float*)d_in[1];
    const float* bq = (const float*)d_in[2];
    const float* Wk = (const float*)d_in[3];
    const float* bk = (const float*)d_in[4];
    const float* Wv = (const float*)d_in[5];
    const float* bv = (const float*)d_in[6];
    const float* Wo = (const float*)d_in[7];
    const float* bo = (const float*)d_in[8];
    float* out = (float*)d_out;

    __half *Xp, *Wp, *Qp, *Kp, *Vp, *Cp;
    cudaGetSymbolAddress((void**)&Xp, g_X);
    cudaGetSymbolAddress((void**)&Wp, g_Wh);
    cudaGetSymbolAddress((void**)&Qp, g_Q);
    cudaGetSymbolAddress((void**)&Kp, g_K);
    cudaGetSymbolAddress((void**)&Vp, g_V);
    cudaGetSymbolAddress((void**)&Cp, g_C);

    const int gemm_smem = NSTG*GSTAGE_B + 512;   // 82432
    const int attn_smem = 36864;
    cudaFuncSetAttribute(gemm_qkv, cudaFuncAttributeMaxDynamicSharedMemorySize, gemm_smem);
    cudaFuncSetAttribute(gemm_out, cudaFuncAttributeMaxDynamicSharedMemorySize, gemm_smem);
    cudaFuncSetAttribute(attn_mma5, cudaFuncAttributeMaxDynamicSharedMemorySize, attn_smem);

    cvt_inputs<<<5120, 256>>>(x, Wq, Wk, Wv, Wo, Xp, Wp);

    gemm_qkv<<<dim3(MT/128, HID/128, 3), 256, gemm_smem>>>(
        Xp, Wp, bq, bk, bv, Qp, Kp, Vp);

    attn_mma5<<<dim3(SS/128, HH, BB), 256, attn_smem>>>(Qp, Kp, Vp, Cp);

    gemm_out<<<dim3(MT/128, HID/128), 256, gemm_smem>>>(Cp, Wp + 3*HID*HID, bo, out);
}

// round 11
// speedup vs baseline: 10.6363x; 1.0627x over previous
#include <cuda_runtime.h>
#include <cuda_fp16.h>
#include <cstdint>

// ---------------- problem constants ----------------
#define BB 4
#define SS 2048
#define HH 8
#define DD 64
#define HID 512
#define MT (BB*SS)   // 8192

// scratch (all fp16 intermediates)
__device__ __half g_X[MT*HID];        // x fp16
__device__ __half g_Wh[4*HID*HID];    // Wq,Wk,Wv,Wo fp16
__device__ __half g_Q[MT*HID];        // [b,h,s,d] pre-scaled by 0.125*log2e
__device__ __half g_K[MT*HID];        // [b,h,s,d]
__device__ __half g_V[MT*HID];        // [b,h,s,d]
__device__ __half g_C[MT*HID];        // ctx [b,s,hid] fp16

#define QSCALE 0.18033688011112042f   // 0.125 * log2(e)

__device__ __forceinline__ float ex2(float x){
    float r; asm("ex2.approx.ftz.f32 %0, %1;" : "=f"(r) : "f"(x)); return r;
}
__device__ __forceinline__ uint32_t pkhf(float lo, float hi){
    uint32_t d; asm("cvt.rn.f16x2.f32 %0, %1, %2;" : "=r"(d) : "f"(hi), "f"(lo)); return d;
}
__device__ __forceinline__ uint32_t smem_u32(const void* p){
    uint32_t a;
    asm("{ .reg .u64 t; cvta.to.shared.u64 t, %1; cvt.u32.u64 %0, t; }" : "=r"(a) : "l"(p));
    return a;
}
__device__ __forceinline__ void cpasync16(uint32_t dst, const void* src){
    asm volatile("cp.async.cg.shared.global [%0], [%1], 16;" :: "r"(dst), "l"(src) : "memory");
}
#define CP_COMMIT() asm volatile("cp.async.commit_group;" ::: "memory")
#define CP_WAIT0()  asm volatile("cp.async.wait_group 0;" ::: "memory")

// mma.sync m16n8k16 f16 (fp32 accumulate)
__device__ __forceinline__ void mma16(float* c, const uint32_t* a, const uint32_t* b){
    asm volatile("mma.sync.aligned.m16n8k16.row.col.f32.f16.f16.f32 "
        "{%0,%1,%2,%3}, {%4,%5,%6,%7}, {%8,%9}, {%0,%1,%2,%3};"
        : "+f"(c[0]), "+f"(c[1]), "+f"(c[2]), "+f"(c[3])
        : "r"(a[0]), "r"(a[1]), "r"(a[2]), "r"(a[3]), "r"(b[0]), "r"(b[1]));
}
__device__ __forceinline__ void ldsm4(uint32_t* r, uint32_t addr){
    asm volatile("ldmatrix.sync.aligned.m8n8.x4.shared.b16 {%0,%1,%2,%3}, [%4];"
        : "=r"(r[0]), "=r"(r[1]), "=r"(r[2]), "=r"(r[3]) : "r"(addr));
}
__device__ __forceinline__ void ldsm4t(uint32_t* r, uint32_t addr){
    asm volatile("ldmatrix.sync.aligned.m8n8.x4.trans.shared.b16 {%0,%1,%2,%3}, [%4];"
        : "=r"(r[0]), "=r"(r[1]), "=r"(r[2]), "=r"(r[3]) : "r"(addr));
}

// ---------------------------------------------------------------------------
// fp32 -> fp16 pre-conversion (rounding points identical to in-GEMM cvt).
// ---------------------------------------------------------------------------
__global__ __launch_bounds__(256)
void cvt_inputs(const float* __restrict__ x,
                const float* __restrict__ Wq, const float* __restrict__ Wk,
                const float* __restrict__ Wv, const float* __restrict__ Wo,
                __half* __restrict__ Xh, __half* __restrict__ Wh)
{
    const int flat = blockIdx.x * 256 + threadIdx.x;   // float4 index
    const float* src; uint2* dst; int off;
    if (flat < 1048576) { src = x; dst = (uint2*)Xh; off = flat; }
    else {
        const int w = (flat - 1048576) >> 16;
        off = (flat - 1048576) & 65535;
        src = (w == 0) ? Wq : (w == 1) ? Wk : (w == 2) ? Wv : Wo;
        dst = (uint2*)(Wh + (size_t)w * HID * HID);
    }
    float4 v = ((const float4*)src)[off];
    dst[off] = make_uint2(pkhf(v.x, v.y), pkhf(v.z, v.w));
}

// ---------------------------------------------------------------------------
// GEMM core (fp16 in gmem): out = A[M,512] @ W[Nblk,512]^T + bias.
// CTA 128x128, BK=64, 8 warps = 4(M) x 2(N).  2-stage cp.async pipeline with
// ONE __syncthreads per chunk (next-stage cp issued right after wait+sync).
// Tile stride 72 halves = 144 B (9r mod 8 permutation -> LDSM conflict-free).
// MODE 0: fp32 [m][512]   MODE 1: K fp16 [b,h,s,d]   MODE 2: Q scaled fp16
// MODE 3: V fp16 [b,h,s,d]
// ---------------------------------------------------------------------------
#define BK 64
#define GSTR_B 144
#define GAB_B (128*GSTR_B)       // per-matrix stage bytes = 18432
#define GSTAGE_B (2*GAB_B)       // 36864
#define NCH (HID/BK)             // 8

template<int MODE>
__device__ __forceinline__ void gemm_core(
    const __half* __restrict__ A, const __half* __restrict__ W,
    const float* __restrict__ bias, void* __restrict__ outv,
    char* smraw, int m0, int n0)
{
    float* bs = (float*)(smraw + 2*GSTAGE_B);
    const uint32_t sb = smem_u32(smraw);

    const int tid = threadIdx.x;
    const int lane = tid & 31, warp = tid >> 5;
    const int g = lane >> 2, t4 = lane & 3;
    const int warpM = warp >> 1, warpN = warp & 1;
    const int lm = lane >> 3, lr8 = lane & 7;
    const uint32_t laneA = ((uint32_t)((lm & 1)*8 + lr8))*GSTR_B + (uint32_t)(lm >> 1)*16;
    const uint32_t laneB = ((uint32_t)((lm >> 1)*8 + lr8))*GSTR_B + (uint32_t)(lm & 1)*16;

    if (tid < 128) bs[tid] = bias[n0 + tid];

    float c[2][8][4];
    #pragma unroll
    for (int i = 0; i < 2; i++)
        #pragma unroll
        for (int j = 0; j < 8; j++)
            #pragma unroll
            for (int k = 0; k < 4; k++) c[i][j][k] = 0.0f;

    // cp.async assignment: 4 chunks A + 4 chunks W (16B each) per stage
    const __half* Abase = A + (size_t)m0 * HID;
    const __half* Wbase = W + (size_t)n0 * HID;

    // prologue: chunk 0 -> stage 0
    #pragma unroll
    for (int i = 0; i < 4; i++) {
        const int cc = tid + i*256;
        const int row = cc >> 3, col = cc & 7;
        cpasync16(sb + row*GSTR_B + col*16, Abase + (size_t)row*HID + col*8);
        cpasync16(sb + GAB_B + row*GSTR_B + col*16, Wbase + (size_t)row*HID + col*8);
    }
    CP_COMMIT();

    #pragma unroll 1
    for (int ch = 0; ch < NCH; ch++) {
        const int cur = ch & 1;
        CP_WAIT0();
        __syncthreads();

        if (ch < NCH-1) {
            const uint32_t st = sb + (cur^1)*GSTAGE_B;
            const int koff = (ch+1)*BK;
            #pragma unroll
            for (int i = 0; i < 4; i++) {
                const int cc = tid + i*256;
                const int row = cc >> 3, col = cc & 7;
                cpasync16(st + row*GSTR_B + col*16, Abase + (size_t)row*HID + koff + col*8);
                cpasync16(st + GAB_B + row*GSTR_B + col*16, Wbase + (size_t)row*HID + koff + col*8);
            }
            CP_COMMIT();
        }

        const uint32_t abase = sb + cur*GSTAGE_B + (uint32_t)(warpM*32)*GSTR_B + laneA;
        const uint32_t bbase = sb + cur*GSTAGE_B + GAB_B + (uint32_t)(warpN*64)*GSTR_B + laneB;
        #pragma unroll
        for (int ks = 0; ks < 4; ks++) {      // 4 k-steps of 16
            uint32_t af[2][4];
            ldsm4(af[0], abase + ks*32);
            ldsm4(af[1], abase + 16*GSTR_B + ks*32);
            #pragma unroll
            for (int p = 0; p < 4; p++) {     // 16-n blocks
                uint32_t bf[4];
                ldsm4(bf, bbase + (uint32_t)(p*16)*GSTR_B + ks*32);
                mma16(c[0][2*p],   af[0], bf);
                mma16(c[0][2*p+1], af[0], bf+2);
                mma16(c[1][2*p],   af[1], bf);
                mma16(c[1][2*p+1], af[1], bf+2);
            }
        }
    }

    // epilogue
    #pragma unroll
    for (int mt = 0; mt < 2; mt++) {
        const int row = m0 + warpM*32 + mt*16 + g;
        #pragma unroll
        for (int nt = 0; nt < 8; nt++) {
            const int lc2 = warpN*64 + nt*8 + 2*t4;
            const float b0 = bs[lc2], b1 = bs[lc2+1];
            float2 v0 = make_float2(c[mt][nt][0] + b0, c[mt][nt][1] + b1);
            float2 v1 = make_float2(c[mt][nt][2] + b0, c[mt][nt][3] + b1);
            if (MODE == 2) { v0.x *= QSCALE; v0.y *= QSCALE; v1.x *= QSCALE; v1.y *= QSCALE; }
            if (MODE == 0) {
                float* out = (float*)outv;
                *(float2*)&out[(size_t)row * HID + n0 + lc2] = v0;
                *(float2*)&out[(size_t)(row+8) * HID + n0 + lc2] = v1;
            } else {
                __half* out = (__half*)outv;
                const int bi = row >> 11, s = row & 2047;
                const int cg = n0 + lc2;
                const int h = cg >> 6, d = cg & 63;
                __half* p = out + (((size_t)(bi*HH + h) * SS) + s) * DD + d;
                *(uint32_t*)p = pkhf(v0.x, v0.y);
                *(uint32_t*)(p + 8*DD) = pkhf(v1.x, v1.y);
            }
        }
    }
}

// fused QKV projection
__global__ __launch_bounds__(256, 2)
void gemm_qkv(const __half* __restrict__ x, const __half* __restrict__ Wh,
              const float* __restrict__ bq, const float* __restrict__ bk,
              const float* __restrict__ bv,
              __half* __restrict__ Qp, __half* __restrict__ Kp, __half* __restrict__ Vp)
{
    extern __shared__ char smraw[];
    const int m0 = blockIdx.x << 7, n0 = blockIdx.y << 7;
    if (blockIdx.z == 0)      gemm_core<2>(x, Wh,             bq, Qp, smraw, m0, n0);
    else if (blockIdx.z == 1) gemm_core<1>(x, Wh +   HID*HID, bk, Kp, smraw, m0, n0);
    else                      gemm_core<3>(x, Wh + 2*HID*HID, bv, Vp, smraw, m0, n0);
}

__global__ __launch_bounds__(256, 2)
void gemm_out(const __half* __restrict__ A, const __half* __restrict__ W,
              const float* __restrict__ bias, float* __restrict__ out)
{
    extern __shared__ char smraw[];
    gemm_core<0>(A, W, bias, out, smraw, blockIdx.x << 7, blockIdx.y << 7);
}

// ---------------------------------------------------------------------------
// Flash attention, all-fp16 operands (fp32 accum/softmax).
// S = QK^T fp16 m16n8k16; PV fp16 m16n8k16 with accumulator->A reuse.
// 8 warps x 16 query rows; 64-key tiles, cp.async double buffer.
// l-sum kept as per-thread partials; quad-reduced once in the epilogue.
// ---------------------------------------------------------------------------
#define ASTR_B 144                 // 72 halves
#define ABUF_B (64*ASTR_B)         // 9216
// bytes: K0=0, K1=9216, V0=18432, V1=27648; total 36864
__global__ __launch_bounds__(256, 2)
void attn_mma5(const __half* __restrict__ Q, const __half* __restrict__ K,
               const __half* __restrict__ V, __half* __restrict__ ctx)
{
    extern __shared__ char smraw[];
    const uint32_t sb = smem_u32(smraw);
    const int tid = threadIdx.x;
    const int lane = tid & 31, warp = tid >> 5;
    const int g = lane >> 2, t4 = lane & 3;
    const int lm = lane >> 3, lr8 = lane & 7;
    const uint32_t laneK = ((uint32_t)((lm >> 1)*8 + lr8))*ASTR_B + (uint32_t)(lm & 1)*16;
    const uint32_t laneV = ((uint32_t)((lm & 1)*8 + lr8))*ASTR_B + (uint32_t)(lm >> 1)*16;
    const int b = blockIdx.z, h = blockIdx.y;
    const int q0 = blockIdx.x << 7;

    const __half* Qg = Q + ((size_t)(b*HH + h) * SS + q0) * DD;
    const __half* Kg = K + (size_t)(b*HH + h) * SS * DD;
    const __half* Vg = V + (size_t)(b*HH + h) * SS * DD;

    // Q fragments (rows 16*warp+g, +8): 4 k-steps of 16
    uint32_t qf[4][4];
    {
        const uint32_t* q0p = (const uint32_t*)(Qg + (size_t)(warp*16 + g) * DD);
        const uint32_t* q1p = q0p + 256;   // +8 rows * 64 halves = 256 u32
        #pragma unroll
        for (int ks = 0; ks < 4; ks++) {
            qf[ks][0] = q0p[8*ks + t4];
            qf[ks][1] = q1p[8*ks + t4];
            qf[ks][2] = q0p[8*ks + 4 + t4];
            qf[ks][3] = q1p[8*ks + 4 + t4];
        }
    }

    // prologue
    {
        #pragma unroll
        for (int i = 0; i < 2; i++) {
            const int cc = tid + i*256;
            const int row = cc >> 3, col = cc & 7;
            cpasync16(sb + row*ASTR_B + col*16, Kg + (size_t)row*DD + col*8);
            cpasync16(sb + 18432 + row*ASTR_B + col*16, Vg + (size_t)row*DD + col*8);
        }
        CP_COMMIT();
        CP_WAIT0();
    }
    __syncthreads();

    float o[8][4];
    #pragma unroll
    for (int j = 0; j < 8; j++)
        #pragma unroll
        for (int k = 0; k < 4; k++) o[j][k] = 0.0f;
    float m0r = -1.0e30f, m1r = -1.0e30f, l0r = 0.0f, l1r = 0.0f;

    #pragma unroll 1
    for (int t = 0; t < SS/64; t++) {
        const int cur = t & 1;
        const uint32_t kbase = sb + cur*ABUF_B + laneK;
        const uint32_t vbase = sb + 18432 + cur*ABUF_B + laneV;

        if (t < SS/64 - 1) {
            const uint32_t kd = sb + (cur^1)*ABUF_B;
            const uint32_t vd = sb + 18432 + (cur^1)*ABUF_B;
            const __half* kn = Kg + (size_t)(t+1)*64*DD;
            const __half* vn = Vg + (size_t)(t+1)*64*DD;
            #pragma unroll
            for (int i = 0; i < 2; i++) {
                const int cc = tid + i*256;
                const int row = cc >> 3, col = cc & 7;
                cpasync16(kd + row*ASTR_B + col*16, kn + (size_t)row*DD + col*8);
                cpasync16(vd + row*ASTR_B + col*16, vn + (size_t)row*DD + col*8);
            }
            CP_COMMIT();
        }

        // S = Q K^T
        float sc[8][4];
        #pragma unroll
        for (int j = 0; j < 8; j++)
            #pragma unroll
            for (int k = 0; k < 4; k++) sc[j][k] = 0.0f;
        #pragma unroll
        for (int ks = 0; ks < 4; ks++) {
            #pragma unroll
            for (int p = 0; p < 4; p++) {
                uint32_t bf[4];
                ldsm4(bf, kbase + (uint32_t)(p*16)*ASTR_B + ks*32);
                mma16(sc[2*p],   qf[ks], bf);
                mma16(sc[2*p+1], qf[ks], bf+2);
            }
        }

        // online softmax (base-2), rows g and g+8
        float mx0 = -1.0e30f, mx1 = -1.0e30f;
        #pragma unroll
        for (int nt = 0; nt < 8; nt++) {
            mx0 = fmaxf(mx0, fmaxf(sc[nt][0], sc[nt][1]));
            mx1 = fmaxf(mx1, fmaxf(sc[nt][2], sc[nt][3]));
        }
        mx0 = fmaxf(mx0, __shfl_xor_sync(0xffffffffu, mx0, 1));
        mx0 = fmaxf(mx0, __shfl_xor_sync(0xffffffffu, mx0, 2));
        mx1 = fmaxf(mx1, __shfl_xor_sync(0xffffffffu, mx1, 1));
        mx1 = fmaxf(mx1, __shfl_xor_sync(0xffffffffu, mx1, 2));
        const float mn0 = fmaxf(m0r, mx0), mn1 = fmaxf(m1r, mx1);
        const float corr0 = ex2(m0r - mn0), corr1 = ex2(m1r - mn1);
        m0r = mn0; m1r = mn1;
        float sum0 = 0.0f, sum1 = 0.0f;
        #pragma unroll
        for (int nt = 0; nt < 8; nt++) {
            sc[nt][0] = ex2(sc[nt][0] - mn0);
            sc[nt][1] = ex2(sc[nt][1] - mn0);
            sc[nt][2] = ex2(sc[nt][2] - mn1);
            sc[nt][3] = ex2(sc[nt][3] - mn1);
            sum0 += sc[nt][0] + sc[nt][1];
            sum1 += sc[nt][2] + sc[nt][3];
        }
        // per-thread partial l (quad-reduced in epilogue; corr is quad-uniform)
        l0r = l0r * corr0 + sum0;
        l1r = l1r * corr1 + sum1;

        #pragma unroll
        for (int nt = 0; nt < 8; nt++) {
            o[nt][0] *= corr0; o[nt][1] *= corr0;
            o[nt][2] *= corr1; o[nt][3] *= corr1;
        }

        // PV: O += P V
        #pragma unroll
        for (int j = 0; j < 4; j++) {
            uint32_t af[4];
            af[0] = pkhf(sc[2*j][0],   sc[2*j][1]);
            af[1] = pkhf(sc[2*j][2],   sc[2*j][3]);
            af[2] = pkhf(sc[2*j+1][0], sc[2*j+1][1]);
            af[3] = pkhf(sc[2*j+1][2], sc[2*j+1][3]);
            #pragma unroll
            for (int p = 0; p < 4; p++) {
                uint32_t bf[4];
                ldsm4t(bf, vbase + (uint32_t)(j*16)*ASTR_B + p*32);
                mma16(o[2*p],   af, bf);
                mma16(o[2*p+1], af, bf+2);
            }
        }

        CP_WAIT0();
        __syncthreads();
    }

    // epilogue: quad-reduce l, normalize, write ctx fp16 [b, s, hid]
    l0r += __shfl_xor_sync(0xffffffffu, l0r, 1);
    l0r += __shfl_xor_sync(0xffffffffu, l0r, 2);
    l1r += __shfl_xor_sync(0xffffffffu, l1r, 1);
    l1r += __shfl_xor_sync(0xffffffffu, l1r, 2);
    const float inv0 = 1.0f / l0r, inv1 = 1.0f / l1r;
    const int row = q0 + warp*16 + g;
    #pragma unroll
    for (int nt = 0; nt < 8; nt++) {
        const int d = 8*nt + 2*t4;
        __half* p = ctx + ((size_t)b * SS + row) * HID + h*DD + d;
        *(uint32_t*)p = pkhf(o[nt][0]*inv0, o[nt][1]*inv0);
        *(uint32_t*)(p + 8*HID) = pkhf(o[nt][2]*inv1, o[nt][3]*inv1);
    }
}

// ---------------------------------------------------------------------------
extern "C" void kernel_launch(void* const* d_in, const int* in_sizes, int n_in,
                              void* d_out, int out_size)
{
    (void)in_sizes; (void)n_in; (void)out_size;
    const float* x  = (const float*)d_in[0];
    const float* Wq = (const float*)d_in[1];
    const float* bq = (const float*)d_in[2];
    const float* Wk = (const float*)d_in[3];
    const float* bk = (const float*)d_in[4];
    const float* Wv = (const float*)d_in[5];
    const float* bv = (const float*)d_in[6];
    const float* Wo = (const float*)d_in[7];
    const float* bo = (const float*)d_in[8];
    float* out = (float*)d_out;

    __half *Xp, *Wp, *Qp, *Kp, *Vp, *Cp;
    cudaGetSymbolAddress((void**)&Xp, g_X);
    cudaGetSymbolAddress((void**)&Wp, g_Wh);
    cudaGetSymbolAddress((void**)&Qp, g_Q);
    cudaGetSymbolAddress((void**)&Kp, g_K);
    cudaGetSymbolAddress((void**)&Vp, g_V);
    cudaGetSymbolAddress((void**)&Cp, g_C);

    const int gemm_smem = 2*GSTAGE_B + 512;   // 74240
    const int attn_smem = 36864;
    cudaFuncSetAttribute(gemm_qkv, cudaFuncAttributeMaxDynamicSharedMemorySize, gemm_smem);
    cudaFuncSetAttribute(gemm_out, cudaFuncAttributeMaxDynamicSharedMemorySize, gemm_smem);
    cudaFuncSetAttribute(attn_mma5, cudaFuncAttributeMaxDynamicSharedMemorySize, attn_smem);

    cvt_inputs<<<5120, 256>>>(x, Wq, Wk, Wv, Wo, Xp, Wp);

    gemm_qkv<<<dim3(MT/128, HID/128, 3), 256, gemm_smem>>>(
        Xp, Wp, bq, bk, bv, Qp, Kp, Vp);

    attn_mma5<<<dim3(SS/128, HH, BB), 256, attn_smem>>>(Qp, Kp, Vp, Cp);

    gemm_out<<<dim3(MT/128, HID/128), 256, gemm_smem>>>(Cp, Wp + 3*HID*HID, bo, out);
}